// round 8
// baseline (speedup 1.0000x reference)
#include <cuda_runtime.h>
#include <math.h>
#include <stdint.h>

#define Nn 50000
#define Ee 800000
#define FIN 256
#define D1 128   // H1*HID
#define D2 160   // H2*NCLS
#define NCLS 40
#define CAP 96   // max in-degree (Poisson(16): P(>=96) ~ 1e-18)

typedef unsigned long long u64;

// ---------------- scratch ----------------
__device__ float g_h1[(size_t)Nn * D1];    // x @ W1 (fp32)
__device__ float g_h1a[(size_t)Nn * D1];   // post conv1+elu+ln (gemm2 input)
__device__ float g_h2[(size_t)Nn * D2];    // h1a @ W2 (fp32)
__device__ float g_es1[Nn * 4], g_ed1[Nn * 4];
__device__ float g_es2[Nn * 4], g_ed2[Nn * 4];
__device__ int g_deg[Nn];
__device__ int g_adj[(size_t)Nn * CAP];

// ---------------- helpers ----------------
__device__ __forceinline__ float wsum(float v) {
#pragma unroll
    for (int o = 16; o > 0; o >>= 1) v += __shfl_xor_sync(0xffffffffu, v, o);
    return v;
}
__device__ __forceinline__ float wmax(float v) {
#pragma unroll
    for (int o = 16; o > 0; o >>= 1) v = fmaxf(v, __shfl_xor_sync(0xffffffffu, v, o));
    return v;
}
__device__ __forceinline__ float hsum16(float v) {
#pragma unroll
    for (int o = 1; o < 16; o <<= 1) v += __shfl_xor_sync(0xffffffffu, v, o);
    return v;
}
__device__ __forceinline__ float lrelu(float x) { return x > 0.f ? x : 0.2f * x; }
__device__ __forceinline__ float f2tf(float x) {
    uint32_t r;
    asm("cvt.rna.tf32.f32 %0, %1;" : "=r"(r) : "f"(x));
    return __uint_as_float(r);
}
__device__ __forceinline__ float sel4(float4 v, int i) {
    return i == 0 ? v.x : (i == 1 ? v.y : (i == 2 ? v.z : v.w));
}
// packed f32x2 ops (sm_103a FFMA2)
__device__ __forceinline__ u64 pack2(float x, float y) {
    u64 r;
    asm("mov.b64 %0, {%1, %2};" : "=l"(r) : "f"(x), "f"(y));
    return r;
}
__device__ __forceinline__ void unpack2(u64 v, float& x, float& y) {
    asm("mov.b64 {%0, %1}, %2;" : "=f"(x), "=f"(y) : "l"(v));
}
__device__ __forceinline__ void ffma2(u64& d, u64 a, u64 b) {
    asm("fma.rn.f32x2 %0, %1, %2, %0;" : "+l"(d) : "l"(a), "l"(b));
}

// ---------------- adjacency build ----------------
__global__ void zero_deg_kernel() {
    int i = blockIdx.x * blockDim.x + threadIdx.x;
    if (i < Nn) g_deg[i] = 0;
}
__global__ void fill_kernel(const int* __restrict__ src, const int* __restrict__ dst) {
    int i = blockIdx.x * blockDim.x + threadIdx.x;
    if (i < Ee) {
        int d = dst[i];
        int pos = atomicAdd(&g_deg[d], 1);
        if (pos < CAP) g_adj[(size_t)d * CAP + pos] = src[i];
    }
}

// ---------------- tf32 tensor-core GEMM, double-buffered, fused att ----------
template <int SEL>
__global__ void __launch_bounds__(256, 2) gemm_tc(const float* __restrict__ Aparam,
                                                  const float* __restrict__ B,
                                                  const float* __restrict__ AS,
                                                  const float* __restrict__ AD) {
    constexpr int K = SEL ? D1 : FIN;
    constexpr int NDIM = SEL ? D2 : D1;
    constexpr int NT = SEL ? 80 : 128;
    constexpr int NTILE = NT / 16;
    constexpr int BPAD = NT + 8;
    constexpr int KC = 16;
    constexpr int NITER = K / KC;
    constexpr int BVEC = (KC * NT) / 4;
    const float* __restrict__ A = SEL ? (const float*)g_h1a : Aparam;
    float* __restrict__ C = SEL ? g_h2 : g_h1;
    float* __restrict__ ES = SEL ? g_es2 : g_es1;
    float* __restrict__ ED = SEL ? g_ed2 : g_ed1;

    __shared__ float As[2][128][20];
    __shared__ float Bs[2][KC][BPAD];

    int tid = threadIdx.x;
    int lane = tid & 31, wid = tid >> 5;
    int wm = (wid & 3) * 32;
    int wn = (wid >> 2) * (NT / 2);
    int g = lane >> 2, t = lane & 3;
    int rb = blockIdx.y * 128, cb = blockIdx.x * NT;

    float acc[2][NTILE][4];
#pragma unroll
    for (int mt = 0; mt < 2; mt++)
#pragma unroll
        for (int nt = 0; nt < NTILE; nt++)
#pragma unroll
            for (int q = 0; q < 4; q++) acc[mt][nt][q] = 0.f;

    float4 ra[2], rbv[2];
    int arow[2], acol[2];
#pragma unroll
    for (int q = 0; q < 2; q++) {
        int idx = tid + q * 256;
        arow[q] = idx >> 2;
        acol[q] = (idx & 3) * 4;
    }
    int brow[2], bcol[2];
    bool bval[2];
#pragma unroll
    for (int q = 0; q < 2; q++) {
        int idx = tid + q * 256;
        bval[q] = idx < BVEC;
        brow[q] = idx / (NT / 4);
        bcol[q] = (idx % (NT / 4)) * 4;
    }

    auto loadTile = [&](int k0) {
#pragma unroll
        for (int q = 0; q < 2; q++) {
            float4 v = make_float4(0.f, 0.f, 0.f, 0.f);
            int r = rb + arow[q];
            if (r < Nn) v = *(const float4*)&A[(size_t)r * K + k0 + acol[q]];
            ra[q] = v;
        }
#pragma unroll
        for (int q = 0; q < 2; q++) {
            if (bval[q])
                rbv[q] = *(const float4*)&B[(size_t)(k0 + brow[q]) * NDIM + cb + bcol[q]];
        }
    };
    auto storeTile = [&](int buf) {
#pragma unroll
        for (int q = 0; q < 2; q++) {
            float4 v = ra[q];
            *(float4*)&As[buf][arow[q]][acol[q]] =
                make_float4(f2tf(v.x), f2tf(v.y), f2tf(v.z), f2tf(v.w));
        }
#pragma unroll
        for (int q = 0; q < 2; q++) {
            if (bval[q]) {
                float4 v = rbv[q];
                *(float4*)&Bs[buf][brow[q]][bcol[q]] =
                    make_float4(f2tf(v.x), f2tf(v.y), f2tf(v.z), f2tf(v.w));
            }
        }
    };

    loadTile(0);
    storeTile(0);
    __syncthreads();

    for (int it = 0; it < NITER; it++) {
        int cur = it & 1;
        if (it + 1 < NITER) loadTile((it + 1) * KC);
#pragma unroll
        for (int ks = 0; ks < 2; ks++) {
            int kk = ks * 8;
            uint32_t afr[2][4];
#pragma unroll
            for (int mt = 0; mt < 2; mt++) {
                int m = wm + mt * 16 + g;
                afr[mt][0] = __float_as_uint(As[cur][m][kk + t]);
                afr[mt][1] = __float_as_uint(As[cur][m + 8][kk + t]);
                afr[mt][2] = __float_as_uint(As[cur][m][kk + t + 4]);
                afr[mt][3] = __float_as_uint(As[cur][m + 8][kk + t + 4]);
            }
#pragma unroll
            for (int nt = 0; nt < NTILE; nt++) {
                uint32_t b0 = __float_as_uint(Bs[cur][kk + t][wn + nt * 8 + g]);
                uint32_t b1 = __float_as_uint(Bs[cur][kk + t + 4][wn + nt * 8 + g]);
#pragma unroll
                for (int mt = 0; mt < 2; mt++) {
                    asm volatile(
                        "mma.sync.aligned.m16n8k8.row.col.f32.tf32.tf32.f32 "
                        "{%0,%1,%2,%3}, {%4,%5,%6,%7}, {%8,%9}, {%0,%1,%2,%3};"
                        : "+f"(acc[mt][nt][0]), "+f"(acc[mt][nt][1]),
                          "+f"(acc[mt][nt][2]), "+f"(acc[mt][nt][3])
                        : "r"(afr[mt][0]), "r"(afr[mt][1]), "r"(afr[mt][2]), "r"(afr[mt][3]),
                          "r"(b0), "r"(b1));
                }
            }
        }
        if (it + 1 < NITER) storeTile(1 - cur);
        __syncthreads();
    }

    // fp32 store of activations
#pragma unroll
    for (int mt = 0; mt < 2; mt++) {
        int r0 = rb + wm + mt * 16 + g;
        int r1 = r0 + 8;
#pragma unroll
        for (int nt = 0; nt < NTILE; nt++) {
            int c = cb + wn + nt * 8 + t * 2;
            if (r0 < Nn) *(float2*)&C[(size_t)r0 * NDIM + c] =
                make_float2(acc[mt][nt][0], acc[mt][nt][1]);
            if (r1 < Nn) *(float2*)&C[(size_t)r1 * NDIM + c] =
                make_float2(acc[mt][nt][2], acc[mt][nt][3]);
        }
    }

    // fused attention coefficients
    if (SEL == 0) {
#pragma unroll
        for (int mt = 0; mt < 2; mt++) {
            float esA0 = 0.f, esA1 = 0.f, esB0 = 0.f, esB1 = 0.f;
            float edA0 = 0.f, edA1 = 0.f, edB0 = 0.f, edB1 = 0.f;
#pragma unroll
            for (int nt = 0; nt < NTILE; nt++) {
                int c = wn + nt * 8 + t * 2;
                float a0 = AS[c], a1 = AS[c + 1];
                float d0 = AD[c], d1 = AD[c + 1];
                float e0 = acc[mt][nt][0] * a0 + acc[mt][nt][1] * a1;
                float e1 = acc[mt][nt][2] * a0 + acc[mt][nt][3] * a1;
                float f0 = acc[mt][nt][0] * d0 + acc[mt][nt][1] * d1;
                float f1 = acc[mt][nt][2] * d0 + acc[mt][nt][3] * d1;
                if (nt < 4) { esA0 += e0; esA1 += e1; edA0 += f0; edA1 += f1; }
                else        { esB0 += e0; esB1 += e1; edB0 += f0; edB1 += f1; }
            }
#pragma unroll
            for (int o = 1; o < 4; o <<= 1) {
                esA0 += __shfl_xor_sync(0xffffffffu, esA0, o);
                esA1 += __shfl_xor_sync(0xffffffffu, esA1, o);
                esB0 += __shfl_xor_sync(0xffffffffu, esB0, o);
                esB1 += __shfl_xor_sync(0xffffffffu, esB1, o);
                edA0 += __shfl_xor_sync(0xffffffffu, edA0, o);
                edA1 += __shfl_xor_sync(0xffffffffu, edA1, o);
                edB0 += __shfl_xor_sync(0xffffffffu, edB0, o);
                edB1 += __shfl_xor_sync(0xffffffffu, edB1, o);
            }
            if (t == 0) {
                int hA = wn >> 5;
                int r0 = rb + wm + mt * 16 + g, r1 = r0 + 8;
                if (r0 < Nn) {
                    ES[r0 * 4 + hA] = esA0; ES[r0 * 4 + hA + 1] = esB0;
                    ED[r0 * 4 + hA] = edA0; ED[r0 * 4 + hA + 1] = edB0;
                }
                if (r1 < Nn) {
                    ES[r1 * 4 + hA] = esA1; ES[r1 * 4 + hA + 1] = esB1;
                    ED[r1 * 4 + hA] = edA1; ED[r1 * 4 + hA + 1] = edB1;
                }
            }
        }
    } else {
#pragma unroll
        for (int mt = 0; mt < 2; mt++) {
            float es0 = 0.f, es1 = 0.f, ed0 = 0.f, ed1 = 0.f;
#pragma unroll
            for (int nt = 0; nt < NTILE; nt++) {
                int c = cb + wn + nt * 8 + t * 2;
                float a0 = AS[c], a1 = AS[c + 1];
                float d0 = AD[c], d1 = AD[c + 1];
                es0 += acc[mt][nt][0] * a0 + acc[mt][nt][1] * a1;
                es1 += acc[mt][nt][2] * a0 + acc[mt][nt][3] * a1;
                ed0 += acc[mt][nt][0] * d0 + acc[mt][nt][1] * d1;
                ed1 += acc[mt][nt][2] * d0 + acc[mt][nt][3] * d1;
            }
#pragma unroll
            for (int o = 1; o < 4; o <<= 1) {
                es0 += __shfl_xor_sync(0xffffffffu, es0, o);
                es1 += __shfl_xor_sync(0xffffffffu, es1, o);
                ed0 += __shfl_xor_sync(0xffffffffu, ed0, o);
                ed1 += __shfl_xor_sync(0xffffffffu, ed1, o);
            }
            if (t == 0) {
                int h = (cb + wn) / NCLS;
                int r0 = rb + wm + mt * 16 + g, r1 = r0 + 8;
                if (r0 < Nn) { ES[r0 * 4 + h] = es0; ED[r0 * 4 + h] = ed0; }
                if (r1 < Nn) { ES[r1 * 4 + h] = es1; ED[r1 * 4 + h] = ed1; }
            }
        }
    }
}

// ---------------- agg1: 16 lanes/edge, fp32 float4 gathers + FFMA2 ----------
__global__ void agg1_kernel(const float* __restrict__ b1, const float* __restrict__ g,
                            const float* __restrict__ bb) {
    int node = (blockIdx.x * blockDim.x + threadIdx.x) >> 5;
    if (node >= Nn) return;
    int lane = threadIdx.x & 31;
    int sub = lane >> 4, m = lane & 15;
    int hm = m >> 2;
    const float4* __restrict__ h4 = (const float4*)g_h1;  // 32 float4/row

    float edv = g_ed1[node * 4 + hm];
    float pself = __expf(lrelu(g_es1[node * 4 + hm] + edv));

    u64 acc[4];
    {
        float4 a = h4[(size_t)node * 32 + 2 * m];
        float4 b = h4[(size_t)node * 32 + 2 * m + 1];
        float p0 = (sub == 0) ? pself : 0.f;
        acc[0] = pack2(p0 * a.x, p0 * a.y);
        acc[1] = pack2(p0 * a.z, p0 * a.w);
        acc[2] = pack2(p0 * b.x, p0 * b.y);
        acc[3] = pack2(p0 * b.z, p0 * b.w);
    }
    float dl = (sub == 0 && (m & 3) == 0) ? pself : 0.f;

    int deg = min(g_deg[node], CAP);
    const int* __restrict__ cols = g_adj + (size_t)node * CAP;
#pragma unroll 4
    for (int base = 0; base < deg; base += 2) {
        int j = base + sub;
        bool vld = j < deg;
        int sidx = vld ? cols[j] : 0;
        float p = vld ? __expf(lrelu(g_es1[sidx * 4 + hm] + edv)) : 0.f;
        if ((m & 3) == 0) dl += p;
        u64 p2 = pack2(p, p);
        union { float4 f; u64 u[2]; } A, B;
        A.f = h4[(size_t)sidx * 32 + 2 * m];
        B.f = h4[(size_t)sidx * 32 + 2 * m + 1];
        ffma2(acc[0], p2, A.u[0]);
        ffma2(acc[1], p2, A.u[1]);
        ffma2(acc[2], p2, B.u[0]);
        ffma2(acc[3], p2, B.u[1]);
    }
    float av[8];
#pragma unroll
    for (int i = 0; i < 4; i++) unpack2(acc[i], av[2 * i], av[2 * i + 1]);
#pragma unroll
    for (int i = 0; i < 8; i++) av[i] += __shfl_xor_sync(0xffffffffu, av[i], 16);
    dl += __shfl_xor_sync(0xffffffffu, dl, 16);
    float d = __shfl_sync(0xffffffffu, dl, hm * 4);
    float inv = 1.0f / (d + 1e-16f);

    float4 bq0 = *(const float4*)&b1[8 * m];
    float4 bq1 = *(const float4*)&b1[8 * m + 4];
    float bv[8] = {bq0.x, bq0.y, bq0.z, bq0.w, bq1.x, bq1.y, bq1.z, bq1.w};
    float v[8];
    float s = 0.f;
#pragma unroll
    for (int i = 0; i < 8; i++) {
        float x = av[i] * inv + bv[i];
        v[i] = (x > 0.f) ? x : expm1f(x);
        s += v[i];
    }
    s = hsum16(s);
    float mu = s * (1.0f / 128.0f);
    float vs = 0.f;
#pragma unroll
    for (int i = 0; i < 8; i++) {
        float dd = v[i] - mu;
        vs += dd * dd;
    }
    vs = hsum16(vs) * (1.0f / 128.0f);
    float rs = rsqrtf(vs + 1e-5f);
    if (sub == 0) {
        float4 gq0 = *(const float4*)&g[8 * m];
        float4 gq1 = *(const float4*)&g[8 * m + 4];
        float4 cq0 = *(const float4*)&bb[8 * m];
        float4 cq1 = *(const float4*)&bb[8 * m + 4];
        float* __restrict__ on = g_h1a + (size_t)node * D1 + 8 * m;
        *(float4*)&on[0] = make_float4((v[0] - mu) * rs * gq0.x + cq0.x,
                                       (v[1] - mu) * rs * gq0.y + cq0.y,
                                       (v[2] - mu) * rs * gq0.z + cq0.z,
                                       (v[3] - mu) * rs * gq0.w + cq0.w);
        *(float4*)&on[4] = make_float4((v[4] - mu) * rs * gq1.x + cq1.x,
                                       (v[5] - mu) * rs * gq1.y + cq1.y,
                                       (v[6] - mu) * rs * gq1.z + cq1.z,
                                       (v[7] - mu) * rs * gq1.w + cq1.w);
    }
}

// ---------------- agg2: 16 lanes/edge, fp32 + FFMA2, fused mean+LN+logsm ----
__global__ void agg2_kernel(const float* __restrict__ b2, const float* __restrict__ g,
                            const float* __restrict__ bb, float* __restrict__ out) {
    __shared__ float stage[8][D2];
    int node = (blockIdx.x * blockDim.x + threadIdx.x) >> 5;
    if (node >= Nn) return;
    int lane = threadIdx.x & 31;
    int sub = lane >> 4, m = lane & 15;
    int warp = (threadIdx.x >> 5) & 7;
    int hA = m / 5;
    bool ex = m < 4;
    const float4* __restrict__ h4 = (const float4*)g_h2;  // 40 float4/row
    const float4* __restrict__ es4p = (const float4*)g_es2;

    float4 edq = *(const float4*)&g_ed2[node * 4];
    float edA = sel4(edq, hA);
    float edC = edq.w;
    float4 esq = *(const float4*)&g_es2[node * 4];
    float pselfA = __expf(lrelu(sel4(esq, hA) + edA));
    float pselfC = __expf(lrelu(esq.w + edC));

    u64 acc[4], accx[4];
    {
        float pa = (sub == 0) ? pselfA : 0.f;
        float pc = (sub == 0) ? pselfC : 0.f;
        float4 a = h4[(size_t)node * 40 + 2 * m];
        float4 b = h4[(size_t)node * 40 + 2 * m + 1];
        acc[0] = pack2(pa * a.x, pa * a.y);
        acc[1] = pack2(pa * a.z, pa * a.w);
        acc[2] = pack2(pa * b.x, pa * b.y);
        acc[3] = pack2(pa * b.z, pa * b.w);
        float4 xa = ex ? h4[(size_t)node * 40 + 32 + 2 * m] : make_float4(0.f, 0.f, 0.f, 0.f);
        float4 xb = ex ? h4[(size_t)node * 40 + 33 + 2 * m] : make_float4(0.f, 0.f, 0.f, 0.f);
        accx[0] = pack2(pc * xa.x, pc * xa.y);
        accx[1] = pack2(pc * xa.z, pc * xa.w);
        accx[2] = pack2(pc * xb.x, pc * xb.y);
        accx[3] = pack2(pc * xb.z, pc * xb.w);
    }
    float dl = (sub == 0 && (m % 5) == 0) ? pselfA : 0.f;

    int deg = min(g_deg[node], CAP);
    const int* __restrict__ cols = g_adj + (size_t)node * CAP;
#pragma unroll 4
    for (int base = 0; base < deg; base += 2) {
        int j = base + sub;
        bool vld = j < deg;
        int sidx = vld ? cols[j] : 0;
        float4 e4 = es4p[sidx];
        float pA = vld ? __expf(lrelu(sel4(e4, hA) + edA)) : 0.f;
        float pC = (vld && ex) ? __expf(lrelu(e4.w + edC)) : 0.f;
        if ((m % 5) == 0) dl += pA;
        u64 pA2 = pack2(pA, pA);
        union { float4 f; u64 u[2]; } A, B;
        A.f = h4[(size_t)sidx * 40 + 2 * m];
        B.f = h4[(size_t)sidx * 40 + 2 * m + 1];
        ffma2(acc[0], pA2, A.u[0]);
        ffma2(acc[1], pA2, A.u[1]);
        ffma2(acc[2], pA2, B.u[0]);
        ffma2(acc[3], pA2, B.u[1]);
        if (ex) {
            u64 pC2 = pack2(pC, pC);
            union { float4 f; u64 u[2]; } XA, XB;
            XA.f = h4[(size_t)sidx * 40 + 32 + 2 * m];
            XB.f = h4[(size_t)sidx * 40 + 33 + 2 * m];
            ffma2(accx[0], pC2, XA.u[0]);
            ffma2(accx[1], pC2, XA.u[1]);
            ffma2(accx[2], pC2, XB.u[0]);
            ffma2(accx[3], pC2, XB.u[1]);
        }
    }
    float av[8], axv[8];
#pragma unroll
    for (int i = 0; i < 4; i++) {
        unpack2(acc[i], av[2 * i], av[2 * i + 1]);
        unpack2(accx[i], axv[2 * i], axv[2 * i + 1]);
    }
#pragma unroll
    for (int i = 0; i < 8; i++) {
        av[i] += __shfl_xor_sync(0xffffffffu, av[i], 16);
        axv[i] += __shfl_xor_sync(0xffffffffu, axv[i], 16);
    }
    dl += __shfl_xor_sync(0xffffffffu, dl, 16);
    float dA = __shfl_sync(0xffffffffu, dl, 5 * hA);
    float dC = __shfl_sync(0xffffffffu, dl, 15);
    float invA = 1.0f / (dA + 1e-16f);
    float invC = 1.0f / (dC + 1e-16f);

    if (sub == 0) {
        *(float4*)&stage[warp][8 * m] =
            make_float4(av[0] * invA, av[1] * invA, av[2] * invA, av[3] * invA);
        *(float4*)&stage[warp][8 * m + 4] =
            make_float4(av[4] * invA, av[5] * invA, av[6] * invA, av[7] * invA);
        if (ex) {
            *(float4*)&stage[warp][128 + 8 * m] =
                make_float4(axv[0] * invC, axv[1] * invC, axv[2] * invC, axv[3] * invC);
            *(float4*)&stage[warp][128 + 8 * m + 4] =
                make_float4(axv[4] * invC, axv[5] * invC, axv[6] * invC, axv[7] * invC);
        }
    }
    __syncwarp();

    bool has1 = lane < 8;
    float v0 = 0.f, v1 = 0.f;
#pragma unroll
    for (int hh = 0; hh < 4; hh++) {
        v0 += stage[warp][hh * NCLS + lane];
        if (has1) v1 += stage[warp][hh * NCLS + 32 + lane];
    }
    v0 = 0.25f * v0 + b2[lane];
    if (has1) v1 = 0.25f * v1 + b2[lane + 32];

    float s = wsum(v0 + (has1 ? v1 : 0.f));
    float mu = s * (1.0f / 40.0f);
    float d0 = v0 - mu;
    float d1 = has1 ? (v1 - mu) : 0.f;
    float vs = wsum(d0 * d0 + d1 * d1) * (1.0f / 40.0f);
    float rs = rsqrtf(vs + 1e-5f);
    float y0 = d0 * rs * g[lane] + bb[lane];
    float y1 = has1 ? (d1 * rs * g[lane + 32] + bb[lane + 32]) : -INFINITY;

    float mx = wmax(fmaxf(y0, y1));
    float se = wsum(__expf(y0 - mx) + (has1 ? __expf(y1 - mx) : 0.f));
    float lse = mx + logf(se);
    out[(size_t)node * NCLS + lane] = y0 - lse;
    if (has1) out[(size_t)node * NCLS + lane + 32] = y1 - lse;
}

// ---------------- launch ----------------
extern "C" void kernel_launch(void* const* d_in, const int* in_sizes, int n_in,
                              void* d_out, int out_size) {
    const float* x   = (const float*)d_in[0];
    const int*   ei  = (const int*)d_in[1];
    const float* W1  = (const float*)d_in[2];
    const float* as1 = (const float*)d_in[3];
    const float* ad1 = (const float*)d_in[4];
    const float* b1  = (const float*)d_in[5];
    const float* W2  = (const float*)d_in[6];
    const float* as2 = (const float*)d_in[7];
    const float* ad2 = (const float*)d_in[8];
    const float* b2  = (const float*)d_in[9];
    const float* ln0g = (const float*)d_in[10];
    const float* ln0b = (const float*)d_in[11];
    const float* ln1g = (const float*)d_in[12];
    const float* ln1b = (const float*)d_in[13];
    float* out = (float*)d_out;

    const int* srcp = ei;
    const int* dstp = ei + Ee;

    zero_deg_kernel<<<(Nn + 255) / 256, 256>>>();
    fill_kernel<<<(Ee + 255) / 256, 256>>>(srcp, dstp);

    {
        dim3 grid(1, (Nn + 127) / 128);
        gemm_tc<0><<<grid, 256>>>(x, W1, as1, ad1);
    }
    agg1_kernel<<<(Nn * 32 + 255) / 256, 256>>>(b1, ln0g, ln0b);

    {
        dim3 grid(2, (Nn + 127) / 128);
        gemm_tc<1><<<grid, 256>>>(nullptr, W2, as2, ad2);
    }
    agg2_kernel<<<(Nn * 32 + 255) / 256, 256>>>(b2, ln1g, ln1b, out);
}

// round 9
// speedup vs baseline: 1.0327x; 1.0327x over previous
#include <cuda_runtime.h>
#include <cuda_fp16.h>
#include <math.h>
#include <stdint.h>

#define Nn 50000
#define Ee 800000
#define FIN 256
#define D1 128   // H1*HID
#define D2 160   // H2*NCLS
#define NCLS 40
#define CAP 96   // max in-degree (Poisson(16): P(>=96) ~ 1e-18)

// ---------------- scratch ----------------
__device__ __half g_h1h[(size_t)Nn * D1];   // x @ W1 (fp16)
__device__ float g_h1a[(size_t)Nn * D1];    // post conv1+elu+ln (fp32, gemm2 input)
__device__ __half g_h2h[(size_t)Nn * D2];   // h1a @ W2 (fp16)
__device__ float g_es1[Nn * 4], g_ed1[Nn * 4];
__device__ float g_es2[Nn * 4], g_ed2[Nn * 4];
__device__ int g_deg[Nn];
__device__ int g_adj[(size_t)Nn * CAP];

// ---------------- helpers ----------------
__device__ __forceinline__ float wsum(float v) {
#pragma unroll
    for (int o = 16; o > 0; o >>= 1) v += __shfl_xor_sync(0xffffffffu, v, o);
    return v;
}
__device__ __forceinline__ float wmax(float v) {
#pragma unroll
    for (int o = 16; o > 0; o >>= 1) v = fmaxf(v, __shfl_xor_sync(0xffffffffu, v, o));
    return v;
}
__device__ __forceinline__ float lrelu(float x) { return fmaxf(x, 0.2f * x); }
__device__ __forceinline__ float f2tf(float x) {
    uint32_t r;
    asm("cvt.rna.tf32.f32 %0, %1;" : "=r"(r) : "f"(x));
    return __uint_as_float(r);
}
__device__ __forceinline__ float sel4(float4 v, int i) {
    return i == 0 ? v.x : (i == 1 ? v.y : (i == 2 ? v.z : v.w));
}

// ---------------- adjacency build ----------------
__global__ void zero_deg_kernel() {
    int i = blockIdx.x * blockDim.x + threadIdx.x;
    if (i < Nn) g_deg[i] = 0;
}
__global__ void fill_kernel(const int* __restrict__ src, const int* __restrict__ dst) {
    int i = blockIdx.x * blockDim.x + threadIdx.x;
    if (i < Ee) {
        int d = dst[i];
        int pos = atomicAdd(&g_deg[d], 1);
        if (pos < CAP) g_adj[(size_t)d * CAP + pos] = src[i];
    }
}

// ---------------- tf32 tensor-core GEMM, double-buffered, fp16 out + fused att ----
template <int SEL>
__global__ void __launch_bounds__(256, 2) gemm_tc(const float* __restrict__ Aparam,
                                                  const float* __restrict__ B,
                                                  const float* __restrict__ AS,
                                                  const float* __restrict__ AD) {
    constexpr int K = SEL ? D1 : FIN;
    constexpr int NDIM = SEL ? D2 : D1;
    constexpr int NT = SEL ? 80 : 128;
    constexpr int NTILE = NT / 16;
    constexpr int BPAD = NT + 8;
    constexpr int KC = 16;
    constexpr int NITER = K / KC;
    constexpr int BVEC = (KC * NT) / 4;
    const float* __restrict__ A = SEL ? (const float*)g_h1a : Aparam;
    __half* __restrict__ C = SEL ? g_h2h : g_h1h;
    float* __restrict__ ES = SEL ? g_es2 : g_es1;
    float* __restrict__ ED = SEL ? g_ed2 : g_ed1;

    __shared__ float As[2][128][20];
    __shared__ float Bs[2][KC][BPAD];

    int tid = threadIdx.x;
    int lane = tid & 31, wid = tid >> 5;
    int wm = (wid & 3) * 32;
    int wn = (wid >> 2) * (NT / 2);
    int g = lane >> 2, t = lane & 3;
    int rb = blockIdx.y * 128, cb = blockIdx.x * NT;

    float acc[2][NTILE][4];
#pragma unroll
    for (int mt = 0; mt < 2; mt++)
#pragma unroll
        for (int nt = 0; nt < NTILE; nt++)
#pragma unroll
            for (int q = 0; q < 4; q++) acc[mt][nt][q] = 0.f;

    float4 ra[2], rbv[2];
    int arow[2], acol[2];
#pragma unroll
    for (int q = 0; q < 2; q++) {
        int idx = tid + q * 256;
        arow[q] = idx >> 2;
        acol[q] = (idx & 3) * 4;
    }
    int brow[2], bcol[2];
    bool bval[2];
#pragma unroll
    for (int q = 0; q < 2; q++) {
        int idx = tid + q * 256;
        bval[q] = idx < BVEC;
        brow[q] = idx / (NT / 4);
        bcol[q] = (idx % (NT / 4)) * 4;
    }

    auto loadTile = [&](int k0) {
#pragma unroll
        for (int q = 0; q < 2; q++) {
            float4 v = make_float4(0.f, 0.f, 0.f, 0.f);
            int r = rb + arow[q];
            if (r < Nn) v = *(const float4*)&A[(size_t)r * K + k0 + acol[q]];
            ra[q] = v;
        }
#pragma unroll
        for (int q = 0; q < 2; q++) {
            if (bval[q])
                rbv[q] = *(const float4*)&B[(size_t)(k0 + brow[q]) * NDIM + cb + bcol[q]];
        }
    };
    auto storeTile = [&](int buf) {
#pragma unroll
        for (int q = 0; q < 2; q++) {
            float4 v = ra[q];
            *(float4*)&As[buf][arow[q]][acol[q]] =
                make_float4(f2tf(v.x), f2tf(v.y), f2tf(v.z), f2tf(v.w));
        }
#pragma unroll
        for (int q = 0; q < 2; q++) {
            if (bval[q]) {
                float4 v = rbv[q];
                *(float4*)&Bs[buf][brow[q]][bcol[q]] =
                    make_float4(f2tf(v.x), f2tf(v.y), f2tf(v.z), f2tf(v.w));
            }
        }
    };

    loadTile(0);
    storeTile(0);
    __syncthreads();

    for (int it = 0; it < NITER; it++) {
        int cur = it & 1;
        if (it + 1 < NITER) loadTile((it + 1) * KC);
#pragma unroll
        for (int ks = 0; ks < 2; ks++) {
            int kk = ks * 8;
            uint32_t afr[2][4];
#pragma unroll
            for (int mt = 0; mt < 2; mt++) {
                int m = wm + mt * 16 + g;
                afr[mt][0] = __float_as_uint(As[cur][m][kk + t]);
                afr[mt][1] = __float_as_uint(As[cur][m + 8][kk + t]);
                afr[mt][2] = __float_as_uint(As[cur][m][kk + t + 4]);
                afr[mt][3] = __float_as_uint(As[cur][m + 8][kk + t + 4]);
            }
#pragma unroll
            for (int nt = 0; nt < NTILE; nt++) {
                uint32_t b0 = __float_as_uint(Bs[cur][kk + t][wn + nt * 8 + g]);
                uint32_t b1 = __float_as_uint(Bs[cur][kk + t + 4][wn + nt * 8 + g]);
#pragma unroll
                for (int mt = 0; mt < 2; mt++) {
                    asm volatile(
                        "mma.sync.aligned.m16n8k8.row.col.f32.tf32.tf32.f32 "
                        "{%0,%1,%2,%3}, {%4,%5,%6,%7}, {%8,%9}, {%0,%1,%2,%3};"
                        : "+f"(acc[mt][nt][0]), "+f"(acc[mt][nt][1]),
                          "+f"(acc[mt][nt][2]), "+f"(acc[mt][nt][3])
                        : "r"(afr[mt][0]), "r"(afr[mt][1]), "r"(afr[mt][2]), "r"(afr[mt][3]),
                          "r"(b0), "r"(b1));
                }
            }
        }
        if (it + 1 < NITER) storeTile(1 - cur);
        __syncthreads();
    }

    __half2* __restrict__ C2 = (__half2*)C;
#pragma unroll
    for (int mt = 0; mt < 2; mt++) {
        int r0 = rb + wm + mt * 16 + g;
        int r1 = r0 + 8;
#pragma unroll
        for (int nt = 0; nt < NTILE; nt++) {
            int c = cb + wn + nt * 8 + t * 2;
            if (r0 < Nn) C2[(size_t)r0 * (NDIM / 2) + c / 2] =
                __floats2half2_rn(acc[mt][nt][0], acc[mt][nt][1]);
            if (r1 < Nn) C2[(size_t)r1 * (NDIM / 2) + c / 2] =
                __floats2half2_rn(acc[mt][nt][2], acc[mt][nt][3]);
        }
    }

    // fused attention coefficients
    if (SEL == 0) {
#pragma unroll
        for (int mt = 0; mt < 2; mt++) {
            float esA0 = 0.f, esA1 = 0.f, esB0 = 0.f, esB1 = 0.f;
            float edA0 = 0.f, edA1 = 0.f, edB0 = 0.f, edB1 = 0.f;
#pragma unroll
            for (int nt = 0; nt < NTILE; nt++) {
                int c = wn + nt * 8 + t * 2;
                float a0 = AS[c], a1 = AS[c + 1];
                float d0 = AD[c], d1 = AD[c + 1];
                float e0 = acc[mt][nt][0] * a0 + acc[mt][nt][1] * a1;
                float e1 = acc[mt][nt][2] * a0 + acc[mt][nt][3] * a1;
                float f0 = acc[mt][nt][0] * d0 + acc[mt][nt][1] * d1;
                float f1 = acc[mt][nt][2] * d0 + acc[mt][nt][3] * d1;
                if (nt < 4) { esA0 += e0; esA1 += e1; edA0 += f0; edA1 += f1; }
                else        { esB0 += e0; esB1 += e1; edB0 += f0; edB1 += f1; }
            }
#pragma unroll
            for (int o = 1; o < 4; o <<= 1) {
                esA0 += __shfl_xor_sync(0xffffffffu, esA0, o);
                esA1 += __shfl_xor_sync(0xffffffffu, esA1, o);
                esB0 += __shfl_xor_sync(0xffffffffu, esB0, o);
                esB1 += __shfl_xor_sync(0xffffffffu, esB1, o);
                edA0 += __shfl_xor_sync(0xffffffffu, edA0, o);
                edA1 += __shfl_xor_sync(0xffffffffu, edA1, o);
                edB0 += __shfl_xor_sync(0xffffffffu, edB0, o);
                edB1 += __shfl_xor_sync(0xffffffffu, edB1, o);
            }
            if (t == 0) {
                int hA = wn >> 5;
                int r0 = rb + wm + mt * 16 + g, r1 = r0 + 8;
                if (r0 < Nn) {
                    ES[r0 * 4 + hA] = esA0; ES[r0 * 4 + hA + 1] = esB0;
                    ED[r0 * 4 + hA] = edA0; ED[r0 * 4 + hA + 1] = edB0;
                }
                if (r1 < Nn) {
                    ES[r1 * 4 + hA] = esA1; ES[r1 * 4 + hA + 1] = esB1;
                    ED[r1 * 4 + hA] = edA1; ED[r1 * 4 + hA + 1] = edB1;
                }
            }
        }
    } else {
#pragma unroll
        for (int mt = 0; mt < 2; mt++) {
            float es0 = 0.f, es1 = 0.f, ed0 = 0.f, ed1 = 0.f;
#pragma unroll
            for (int nt = 0; nt < NTILE; nt++) {
                int c = cb + wn + nt * 8 + t * 2;
                float a0 = AS[c], a1 = AS[c + 1];
                float d0 = AD[c], d1 = AD[c + 1];
                es0 += acc[mt][nt][0] * a0 + acc[mt][nt][1] * a1;
                es1 += acc[mt][nt][2] * a0 + acc[mt][nt][3] * a1;
                ed0 += acc[mt][nt][0] * d0 + acc[mt][nt][1] * d1;
                ed1 += acc[mt][nt][2] * d0 + acc[mt][nt][3] * d1;
            }
#pragma unroll
            for (int o = 1; o < 4; o <<= 1) {
                es0 += __shfl_xor_sync(0xffffffffu, es0, o);
                es1 += __shfl_xor_sync(0xffffffffu, es1, o);
                ed0 += __shfl_xor_sync(0xffffffffu, ed0, o);
                ed1 += __shfl_xor_sync(0xffffffffu, ed1, o);
            }
            if (t == 0) {
                int h = (cb + wn) / NCLS;
                int r0 = rb + wm + mt * 16 + g, r1 = r0 + 8;
                if (r0 < Nn) { ES[r0 * 4 + h] = es0; ED[r0 * 4 + h] = ed0; }
                if (r1 < Nn) { ES[r1 * 4 + h] = es1; ED[r1 * 4 + h] = ed1; }
            }
        }
    }
}

// ---------------- agg1: 8 lanes/edge, 4 edges/step, fp16, fused ELU+LN --------
__global__ void agg1_kernel(const float* __restrict__ b1, const float* __restrict__ g,
                            const float* __restrict__ bb) {
    int node = (blockIdx.x * blockDim.x + threadIdx.x) >> 5;
    if (node >= Nn) return;
    int lane = threadIdx.x & 31;
    int sub = lane >> 3, m = lane & 7;
    int hm = m >> 1;  // head of my 16 channels
    const float4* __restrict__ h4 = (const float4*)g_h1h;  // 16 float4/row

    float edv = g_ed1[node * 4 + hm];
    float x0 = g_es1[node * 4 + hm] + edv;
    float pself = __expf(lrelu(x0));

    float acc[16];
    {
        float4 a = h4[(size_t)node * 16 + 2 * m];
        float4 b = h4[(size_t)node * 16 + 2 * m + 1];
        const __half2* ha = (const __half2*)&a;
        const __half2* hb = (const __half2*)&b;
        float p0 = (sub == 0) ? pself : 0.f;
#pragma unroll
        for (int i = 0; i < 4; i++) {
            float2 f = __half22float2(ha[i]);
            acc[2 * i] = p0 * f.x;
            acc[2 * i + 1] = p0 * f.y;
        }
#pragma unroll
        for (int i = 0; i < 4; i++) {
            float2 f = __half22float2(hb[i]);
            acc[8 + 2 * i] = p0 * f.x;
            acc[9 + 2 * i] = p0 * f.y;
        }
    }
    float dl = (sub == 0) ? pself : 0.f;

    int deg = min(g_deg[node], CAP);
    const int* __restrict__ cols = g_adj + (size_t)node * CAP;
#pragma unroll 2
    for (int base = 0; base < deg; base += 4) {
        int j = base + sub;
        bool vld = j < deg;
        int sidx = vld ? cols[j] : 0;
        float x = g_es1[sidx * 4 + hm] + edv;
        float pe = __expf(lrelu(x));
        float p = vld ? pe : 0.f;
        dl += p;
        float4 A = h4[(size_t)sidx * 16 + 2 * m];
        float4 B = h4[(size_t)sidx * 16 + 2 * m + 1];
        const __half2* hA = (const __half2*)&A;
        const __half2* hB = (const __half2*)&B;
#pragma unroll
        for (int i = 0; i < 4; i++) {
            float2 f = __half22float2(hA[i]);
            acc[2 * i] = fmaf(p, f.x, acc[2 * i]);
            acc[2 * i + 1] = fmaf(p, f.y, acc[2 * i + 1]);
        }
#pragma unroll
        for (int i = 0; i < 4; i++) {
            float2 f = __half22float2(hB[i]);
            acc[8 + 2 * i] = fmaf(p, f.x, acc[8 + 2 * i]);
            acc[9 + 2 * i] = fmaf(p, f.y, acc[9 + 2 * i]);
        }
    }
    // reduce across 4 subs
#pragma unroll
    for (int i = 0; i < 16; i++) {
        acc[i] += __shfl_xor_sync(0xffffffffu, acc[i], 8);
        acc[i] += __shfl_xor_sync(0xffffffffu, acc[i], 16);
    }
    dl += __shfl_xor_sync(0xffffffffu, dl, 8);
    dl += __shfl_xor_sync(0xffffffffu, dl, 16);
    float inv = 1.0f / (dl + 1e-16f);

    // bias + ELU
    float bv[16];
#pragma unroll
    for (int q = 0; q < 4; q++) *(float4*)&bv[4 * q] = *(const float4*)&b1[16 * m + 4 * q];
    float v[16];
    float s = 0.f;
#pragma unroll
    for (int i = 0; i < 16; i++) {
        float x = acc[i] * inv + bv[i];
        v[i] = (x > 0.f) ? x : expm1f(x);
        s += v[i];
    }
#pragma unroll
    for (int o = 1; o < 8; o <<= 1) s += __shfl_xor_sync(0xffffffffu, s, o);
    float mu = s * (1.0f / 128.0f);
    float vs = 0.f;
#pragma unroll
    for (int i = 0; i < 16; i++) {
        float dd = v[i] - mu;
        vs += dd * dd;
    }
#pragma unroll
    for (int o = 1; o < 8; o <<= 1) vs += __shfl_xor_sync(0xffffffffu, vs, o);
    float rs = rsqrtf(vs * (1.0f / 128.0f) + 1e-5f);
    if (sub == 0) {
        float* __restrict__ on = g_h1a + (size_t)node * D1 + 16 * m;
#pragma unroll
        for (int q = 0; q < 4; q++) {
            float4 gq = *(const float4*)&g[16 * m + 4 * q];
            float4 cq = *(const float4*)&bb[16 * m + 4 * q];
            *(float4*)&on[4 * q] = make_float4((v[4 * q] - mu) * rs * gq.x + cq.x,
                                               (v[4 * q + 1] - mu) * rs * gq.y + cq.y,
                                               (v[4 * q + 2] - mu) * rs * gq.z + cq.z,
                                               (v[4 * q + 3] - mu) * rs * gq.w + cq.w);
        }
    }
}

// ---------------- agg2: 8 lanes/edge, 4 edges/step, fused mean+LN+logsm ----
__global__ void agg2_kernel(const float* __restrict__ b2, const float* __restrict__ g,
                            const float* __restrict__ bb, float* __restrict__ out) {
    __shared__ float stage[8][D2];
    int node = (blockIdx.x * blockDim.x + threadIdx.x) >> 5;
    if (node >= Nn) return;
    int lane = threadIdx.x & 31;
    int sub = lane >> 3, m = lane & 7;
    int warp = (threadIdx.x >> 5) & 7;
    bool ex = m < 4;
    int h0 = m / 5;          // head of f4 slot m (0 or 1)
    int h1 = (m + 8) / 5;    // head of slot m+8 (1,2,3); slot m+16 -> head 3
    const float4* __restrict__ h4 = (const float4*)g_h2h;  // 20 float4/row
    const float4* __restrict__ es4p = (const float4*)g_es2;

    float4 edq = *(const float4*)&g_ed2[node * 4];
    float4 esq = *(const float4*)&g_es2[node * 4];
    float ps0 = __expf(lrelu(esq.x + edq.x));
    float ps1 = __expf(lrelu(esq.y + edq.y));
    float ps2 = __expf(lrelu(esq.z + edq.z));
    float ps3 = __expf(lrelu(esq.w + edq.w));

    float accA[8], accB[8], accC[8];
    {
        float pa = (sub == 0) ? (h0 == 0 ? ps0 : ps1) : 0.f;
        float pb = (sub == 0) ? (h1 == 1 ? ps1 : (h1 == 2 ? ps2 : ps3)) : 0.f;
        float pc = (sub == 0) ? ps3 : 0.f;
        float4 a = h4[(size_t)node * 20 + m];
        float4 b = h4[(size_t)node * 20 + 8 + m];
        float4 c = ex ? h4[(size_t)node * 20 + 16 + m] : make_float4(0.f, 0.f, 0.f, 0.f);
        const __half2* ha = (const __half2*)&a;
        const __half2* hb = (const __half2*)&b;
        const __half2* hc = (const __half2*)&c;
#pragma unroll
        for (int i = 0; i < 4; i++) {
            float2 fa = __half22float2(ha[i]);
            float2 fb = __half22float2(hb[i]);
            float2 fc = __half22float2(hc[i]);
            accA[2 * i] = pa * fa.x; accA[2 * i + 1] = pa * fa.y;
            accB[2 * i] = pb * fb.x; accB[2 * i + 1] = pb * fb.y;
            accC[2 * i] = pc * fc.x; accC[2 * i + 1] = pc * fc.y;
        }
    }
    float dl0 = (sub == 0) ? ps0 : 0.f;
    float dl1 = (sub == 0) ? ps1 : 0.f;
    float dl2 = (sub == 0) ? ps2 : 0.f;
    float dl3 = (sub == 0) ? ps3 : 0.f;

    int deg = min(g_deg[node], CAP);
    const int* __restrict__ cols = g_adj + (size_t)node * CAP;
#pragma unroll 2
    for (int base = 0; base < deg; base += 4) {
        int j = base + sub;
        bool vld = j < deg;
        int sidx = vld ? cols[j] : 0;
        float4 e4 = es4p[sidx];
        float q0 = __expf(lrelu(e4.x + edq.x));
        float q1 = __expf(lrelu(e4.y + edq.y));
        float q2 = __expf(lrelu(e4.z + edq.z));
        float q3 = __expf(lrelu(e4.w + edq.w));
        float p0 = vld ? q0 : 0.f;
        float p1 = vld ? q1 : 0.f;
        float p2 = vld ? q2 : 0.f;
        float p3 = vld ? q3 : 0.f;
        dl0 += p0; dl1 += p1; dl2 += p2; dl3 += p3;
        float pA = h0 == 0 ? p0 : p1;
        float pB = h1 == 1 ? p1 : (h1 == 2 ? p2 : p3);
        float pC = p3;
        float4 A = h4[(size_t)sidx * 20 + m];
        float4 B = h4[(size_t)sidx * 20 + 8 + m];
        float4 Cc = ex ? h4[(size_t)sidx * 20 + 16 + m] : make_float4(0.f, 0.f, 0.f, 0.f);
        const __half2* hA = (const __half2*)&A;
        const __half2* hB = (const __half2*)&B;
        const __half2* hC = (const __half2*)&Cc;
#pragma unroll
        for (int i = 0; i < 4; i++) {
            float2 fa = __half22float2(hA[i]);
            float2 fb = __half22float2(hB[i]);
            float2 fc = __half22float2(hC[i]);
            accA[2 * i] = fmaf(pA, fa.x, accA[2 * i]);
            accA[2 * i + 1] = fmaf(pA, fa.y, accA[2 * i + 1]);
            accB[2 * i] = fmaf(pB, fb.x, accB[2 * i]);
            accB[2 * i + 1] = fmaf(pB, fb.y, accB[2 * i + 1]);
            accC[2 * i] = fmaf(pC, fc.x, accC[2 * i]);
            accC[2 * i + 1] = fmaf(pC, fc.y, accC[2 * i + 1]);
        }
    }
#pragma unroll
    for (int i = 0; i < 8; i++) {
        accA[i] += __shfl_xor_sync(0xffffffffu, accA[i], 8);
        accA[i] += __shfl_xor_sync(0xffffffffu, accA[i], 16);
        accB[i] += __shfl_xor_sync(0xffffffffu, accB[i], 8);
        accB[i] += __shfl_xor_sync(0xffffffffu, accB[i], 16);
        accC[i] += __shfl_xor_sync(0xffffffffu, accC[i], 8);
        accC[i] += __shfl_xor_sync(0xffffffffu, accC[i], 16);
    }
    dl0 += __shfl_xor_sync(0xffffffffu, dl0, 8);
    dl0 += __shfl_xor_sync(0xffffffffu, dl0, 16);
    dl1 += __shfl_xor_sync(0xffffffffu, dl1, 8);
    dl1 += __shfl_xor_sync(0xffffffffu, dl1, 16);
    dl2 += __shfl_xor_sync(0xffffffffu, dl2, 8);
    dl2 += __shfl_xor_sync(0xffffffffu, dl2, 16);
    dl3 += __shfl_xor_sync(0xffffffffu, dl3, 8);
    dl3 += __shfl_xor_sync(0xffffffffu, dl3, 16);

    float dA = h0 == 0 ? dl0 : dl1;
    float dB = h1 == 1 ? dl1 : (h1 == 2 ? dl2 : dl3);
    float invA = 1.0f / (dA + 1e-16f);
    float invB = 1.0f / (dB + 1e-16f);
    float invC = 1.0f / (dl3 + 1e-16f);

    if (sub == 0) {
        *(float4*)&stage[warp][8 * m] =
            make_float4(accA[0] * invA, accA[1] * invA, accA[2] * invA, accA[3] * invA);
        *(float4*)&stage[warp][8 * m + 4] =
            make_float4(accA[4] * invA, accA[5] * invA, accA[6] * invA, accA[7] * invA);
        *(float4*)&stage[warp][64 + 8 * m] =
            make_float4(accB[0] * invB, accB[1] * invB, accB[2] * invB, accB[3] * invB);
        *(float4*)&stage[warp][64 + 8 * m + 4] =
            make_float4(accB[4] * invB, accB[5] * invB, accB[6] * invB, accB[7] * invB);
        if (ex) {
            *(float4*)&stage[warp][128 + 8 * m] =
                make_float4(accC[0] * invC, accC[1] * invC, accC[2] * invC, accC[3] * invC);
            *(float4*)&stage[warp][128 + 8 * m + 4] =
                make_float4(accC[4] * invC, accC[5] * invC, accC[6] * invC, accC[7] * invC);
        }
    }
    __syncwarp();

    bool has1 = lane < 8;
    float v0 = 0.f, v1 = 0.f;
#pragma unroll
    for (int hh = 0; hh < 4; hh++) {
        v0 += stage[warp][hh * NCLS + lane];
        if (has1) v1 += stage[warp][hh * NCLS + 32 + lane];
    }
    v0 = 0.25f * v0 + b2[lane];
    if (has1) v1 = 0.25f * v1 + b2[lane + 32];

    float s = wsum(v0 + (has1 ? v1 : 0.f));
    float mu = s * (1.0f / 40.0f);
    float d0 = v0 - mu;
    float d1 = has1 ? (v1 - mu) : 0.f;
    float vs = wsum(d0 * d0 + d1 * d1) * (1.0f / 40.0f);
    float rs = rsqrtf(vs + 1e-5f);
    float y0 = d0 * rs * g[lane] + bb[lane];
    float y1 = has1 ? (d1 * rs * g[lane + 32] + bb[lane + 32]) : -INFINITY;

    float mx = wmax(fmaxf(y0, y1));
    float se = wsum(__expf(y0 - mx) + (has1 ? __expf(y1 - mx) : 0.f));
    float lse = mx + logf(se);
    out[(size_t)node * NCLS + lane] = y0 - lse;
    if (has1) out[(size_t)node * NCLS + lane + 32] = y1 - lse;
}

// ---------------- launch ----------------
extern "C" void kernel_launch(void* const* d_in, const int* in_sizes, int n_in,
                              void* d_out, int out_size) {
    const float* x   = (const float*)d_in[0];
    const int*   ei  = (const int*)d_in[1];
    const float* W1  = (const float*)d_in[2];
    const float* as1 = (const float*)d_in[3];
    const float* ad1 = (const float*)d_in[4];
    const float* b1  = (const float*)d_in[5];
    const float* W2  = (const float*)d_in[6];
    const float* as2 = (const float*)d_in[7];
    const float* ad2 = (const float*)d_in[8];
    const float* b2  = (const float*)d_in[9];
    const float* ln0g = (const float*)d_in[10];
    const float* ln0b = (const float*)d_in[11];
    const float* ln1g = (const float*)d_in[12];
    const float* ln1b = (const float*)d_in[13];
    float* out = (float*)d_out;

    const int* srcp = ei;
    const int* dstp = ei + Ee;

    zero_deg_kernel<<<(Nn + 255) / 256, 256>>>();
    fill_kernel<<<(Ee + 255) / 256, 256>>>(srcp, dstp);

    {
        dim3 grid(1, (Nn + 127) / 128);
        gemm_tc<0><<<grid, 256>>>(x, W1, as1, ad1);
    }
    agg1_kernel<<<(Nn * 32 + 255) / 256, 256>>>(b1, ln0g, ln0b);

    {
        dim3 grid(2, (Nn + 127) / 128);
        gemm_tc<1><<<grid, 256>>>(nullptr, W2, as2, ad2);
    }
    agg2_kernel<<<(Nn * 32 + 255) / 256, 256>>>(b2, ln1g, ln1b, out);
}

// round 10
// speedup vs baseline: 1.3296x; 1.2875x over previous
#include <cuda_runtime.h>
#include <cuda_fp16.h>
#include <math.h>
#include <stdint.h>

#define Nn 50000
#define Ee 800000
#define FIN 256
#define D1 128   // H1*HID
#define D2 160   // H2*NCLS
#define NCLS 40
#define CAP 96   // max in-degree (Poisson(16): P(>=96) ~ 1e-18)

// ---------------- scratch ----------------
__device__ __half g_h1h[(size_t)Nn * D1];   // x @ W1 (fp16)
__device__ float g_h1a[(size_t)Nn * D1];    // post conv1+elu+ln (fp32, gemm2 input)
__device__ __half g_h2h[(size_t)Nn * D2];   // h1a @ W2 (fp16, PERMUTED layout, see below)
__device__ float g_es1[Nn * 4], g_ed1[Nn * 4];
__device__ float g_es2[Nn * 4], g_ed2[Nn * 4];
__device__ int g_deg[Nn];
__device__ int g_adj[(size_t)Nn * CAP];

// Permuted h2 layout: half2 slot s = 16*q + m  (m in [0,16), q in [0,5))
// holds logical channel pair c = 2*u, u = (m>>2)*20 + (m&3)*5 + q.
// => lane m in agg2 owns 10 channels all of head (m>>2).

// ---------------- helpers ----------------
__device__ __forceinline__ float wsum(float v) {
#pragma unroll
    for (int o = 16; o > 0; o >>= 1) v += __shfl_xor_sync(0xffffffffu, v, o);
    return v;
}
__device__ __forceinline__ float wmax(float v) {
#pragma unroll
    for (int o = 16; o > 0; o >>= 1) v = fmaxf(v, __shfl_xor_sync(0xffffffffu, v, o));
    return v;
}
__device__ __forceinline__ float lrelu(float x) { return fmaxf(x, 0.2f * x); }
__device__ __forceinline__ float f2tf(float x) {
    uint32_t r;
    asm("cvt.rna.tf32.f32 %0, %1;" : "=r"(r) : "f"(x));
    return __uint_as_float(r);
}

// ---------------- adjacency build ----------------
__global__ void zero_deg_kernel() {
    int i = blockIdx.x * blockDim.x + threadIdx.x;
    if (i < Nn) g_deg[i] = 0;
}
__global__ void fill_kernel(const int* __restrict__ src, const int* __restrict__ dst) {
    int i = blockIdx.x * blockDim.x + threadIdx.x;
    if (i < Ee) {
        int d = dst[i];
        int pos = atomicAdd(&g_deg[d], 1);
        if (pos < CAP) g_adj[(size_t)d * CAP + pos] = src[i];
    }
}

// ---------------- tf32 tensor-core GEMM, double-buffered, fp16 out + fused att ----
template <int SEL>
__global__ void __launch_bounds__(256, 2) gemm_tc(const float* __restrict__ Aparam,
                                                  const float* __restrict__ B,
                                                  const float* __restrict__ AS,
                                                  const float* __restrict__ AD) {
    constexpr int K = SEL ? D1 : FIN;
    constexpr int NDIM = SEL ? D2 : D1;
    constexpr int NT = SEL ? 80 : 128;
    constexpr int NTILE = NT / 16;
    constexpr int BPAD = NT + 8;
    constexpr int KC = 16;
    constexpr int NITER = K / KC;
    constexpr int BVEC = (KC * NT) / 4;
    const float* __restrict__ A = SEL ? (const float*)g_h1a : Aparam;
    __half* __restrict__ C = SEL ? g_h2h : g_h1h;
    float* __restrict__ ES = SEL ? g_es2 : g_es1;
    float* __restrict__ ED = SEL ? g_ed2 : g_ed1;

    __shared__ float As[2][128][20];
    __shared__ float Bs[2][KC][BPAD];

    int tid = threadIdx.x;
    int lane = tid & 31, wid = tid >> 5;
    int wm = (wid & 3) * 32;
    int wn = (wid >> 2) * (NT / 2);
    int g = lane >> 2, t = lane & 3;
    int rb = blockIdx.y * 128, cb = blockIdx.x * NT;

    float acc[2][NTILE][4];
#pragma unroll
    for (int mt = 0; mt < 2; mt++)
#pragma unroll
        for (int nt = 0; nt < NTILE; nt++)
#pragma unroll
            for (int q = 0; q < 4; q++) acc[mt][nt][q] = 0.f;

    float4 ra[2], rbv[2];
    int arow[2], acol[2];
#pragma unroll
    for (int q = 0; q < 2; q++) {
        int idx = tid + q * 256;
        arow[q] = idx >> 2;
        acol[q] = (idx & 3) * 4;
    }
    int brow[2], bcol[2];
    bool bval[2];
#pragma unroll
    for (int q = 0; q < 2; q++) {
        int idx = tid + q * 256;
        bval[q] = idx < BVEC;
        brow[q] = idx / (NT / 4);
        bcol[q] = (idx % (NT / 4)) * 4;
    }

    auto loadTile = [&](int k0) {
#pragma unroll
        for (int q = 0; q < 2; q++) {
            float4 v = make_float4(0.f, 0.f, 0.f, 0.f);
            int r = rb + arow[q];
            if (r < Nn) v = *(const float4*)&A[(size_t)r * K + k0 + acol[q]];
            ra[q] = v;
        }
#pragma unroll
        for (int q = 0; q < 2; q++) {
            if (bval[q])
                rbv[q] = *(const float4*)&B[(size_t)(k0 + brow[q]) * NDIM + cb + bcol[q]];
        }
    };
    auto storeTile = [&](int buf) {
#pragma unroll
        for (int q = 0; q < 2; q++) {
            float4 v = ra[q];
            *(float4*)&As[buf][arow[q]][acol[q]] =
                make_float4(f2tf(v.x), f2tf(v.y), f2tf(v.z), f2tf(v.w));
        }
#pragma unroll
        for (int q = 0; q < 2; q++) {
            if (bval[q]) {
                float4 v = rbv[q];
                *(float4*)&Bs[buf][brow[q]][bcol[q]] =
                    make_float4(f2tf(v.x), f2tf(v.y), f2tf(v.z), f2tf(v.w));
            }
        }
    };

    loadTile(0);
    storeTile(0);
    __syncthreads();

    for (int it = 0; it < NITER; it++) {
        int cur = it & 1;
        if (it + 1 < NITER) loadTile((it + 1) * KC);
#pragma unroll
        for (int ks = 0; ks < 2; ks++) {
            int kk = ks * 8;
            uint32_t afr[2][4];
#pragma unroll
            for (int mt = 0; mt < 2; mt++) {
                int m = wm + mt * 16 + g;
                afr[mt][0] = __float_as_uint(As[cur][m][kk + t]);
                afr[mt][1] = __float_as_uint(As[cur][m + 8][kk + t]);
                afr[mt][2] = __float_as_uint(As[cur][m][kk + t + 4]);
                afr[mt][3] = __float_as_uint(As[cur][m + 8][kk + t + 4]);
            }
#pragma unroll
            for (int nt = 0; nt < NTILE; nt++) {
                uint32_t b0 = __float_as_uint(Bs[cur][kk + t][wn + nt * 8 + g]);
                uint32_t b1 = __float_as_uint(Bs[cur][kk + t + 4][wn + nt * 8 + g]);
#pragma unroll
                for (int mt = 0; mt < 2; mt++) {
                    asm volatile(
                        "mma.sync.aligned.m16n8k8.row.col.f32.tf32.tf32.f32 "
                        "{%0,%1,%2,%3}, {%4,%5,%6,%7}, {%8,%9}, {%0,%1,%2,%3};"
                        : "+f"(acc[mt][nt][0]), "+f"(acc[mt][nt][1]),
                          "+f"(acc[mt][nt][2]), "+f"(acc[mt][nt][3])
                        : "r"(afr[mt][0]), "r"(afr[mt][1]), "r"(afr[mt][2]), "r"(afr[mt][3]),
                          "r"(b0), "r"(b1));
                }
            }
        }
        if (it + 1 < NITER) storeTile(1 - cur);
        __syncthreads();
    }

    __half2* __restrict__ C2 = (__half2*)C;
#pragma unroll
    for (int mt = 0; mt < 2; mt++) {
        int r0 = rb + wm + mt * 16 + g;
        int r1 = r0 + 8;
#pragma unroll
        for (int nt = 0; nt < NTILE; nt++) {
            int c = cb + wn + nt * 8 + t * 2;
            size_t sIdx;
            if (SEL == 0) {
                sIdx = c / 2;
            } else {
                int u = c >> 1;
                int h = u / 20;
                int w = u - 20 * h;
                int mq = w / 5;
                int q = w - 5 * mq;
                sIdx = 16 * q + 4 * h + mq;  // permuted slot
            }
            if (r0 < Nn) C2[(size_t)r0 * (NDIM / 2) + sIdx] =
                __floats2half2_rn(acc[mt][nt][0], acc[mt][nt][1]);
            if (r1 < Nn) C2[(size_t)r1 * (NDIM / 2) + sIdx] =
                __floats2half2_rn(acc[mt][nt][2], acc[mt][nt][3]);
        }
    }

    // fused attention coefficients (logical channel order; uses fp32 accumulators)
    if (SEL == 0) {
#pragma unroll
        for (int mt = 0; mt < 2; mt++) {
            float esA0 = 0.f, esA1 = 0.f, esB0 = 0.f, esB1 = 0.f;
            float edA0 = 0.f, edA1 = 0.f, edB0 = 0.f, edB1 = 0.f;
#pragma unroll
            for (int nt = 0; nt < NTILE; nt++) {
                int c = wn + nt * 8 + t * 2;
                float a0 = AS[c], a1 = AS[c + 1];
                float d0 = AD[c], d1 = AD[c + 1];
                float e0 = acc[mt][nt][0] * a0 + acc[mt][nt][1] * a1;
                float e1 = acc[mt][nt][2] * a0 + acc[mt][nt][3] * a1;
                float f0 = acc[mt][nt][0] * d0 + acc[mt][nt][1] * d1;
                float f1 = acc[mt][nt][2] * d0 + acc[mt][nt][3] * d1;
                if (nt < 4) { esA0 += e0; esA1 += e1; edA0 += f0; edA1 += f1; }
                else        { esB0 += e0; esB1 += e1; edB0 += f0; edB1 += f1; }
            }
#pragma unroll
            for (int o = 1; o < 4; o <<= 1) {
                esA0 += __shfl_xor_sync(0xffffffffu, esA0, o);
                esA1 += __shfl_xor_sync(0xffffffffu, esA1, o);
                esB0 += __shfl_xor_sync(0xffffffffu, esB0, o);
                esB1 += __shfl_xor_sync(0xffffffffu, esB1, o);
                edA0 += __shfl_xor_sync(0xffffffffu, edA0, o);
                edA1 += __shfl_xor_sync(0xffffffffu, edA1, o);
                edB0 += __shfl_xor_sync(0xffffffffu, edB0, o);
                edB1 += __shfl_xor_sync(0xffffffffu, edB1, o);
            }
            if (t == 0) {
                int hA = wn >> 5;
                int r0 = rb + wm + mt * 16 + g, r1 = r0 + 8;
                if (r0 < Nn) {
                    ES[r0 * 4 + hA] = esA0; ES[r0 * 4 + hA + 1] = esB0;
                    ED[r0 * 4 + hA] = edA0; ED[r0 * 4 + hA + 1] = edB0;
                }
                if (r1 < Nn) {
                    ES[r1 * 4 + hA] = esA1; ES[r1 * 4 + hA + 1] = esB1;
                    ED[r1 * 4 + hA] = edA1; ED[r1 * 4 + hA + 1] = edB1;
                }
            }
        }
    } else {
#pragma unroll
        for (int mt = 0; mt < 2; mt++) {
            float es0 = 0.f, es1 = 0.f, ed0 = 0.f, ed1 = 0.f;
#pragma unroll
            for (int nt = 0; nt < NTILE; nt++) {
                int c = cb + wn + nt * 8 + t * 2;
                float a0 = AS[c], a1 = AS[c + 1];
                float d0 = AD[c], d1 = AD[c + 1];
                es0 += acc[mt][nt][0] * a0 + acc[mt][nt][1] * a1;
                es1 += acc[mt][nt][2] * a0 + acc[mt][nt][3] * a1;
                ed0 += acc[mt][nt][0] * d0 + acc[mt][nt][1] * d1;
                ed1 += acc[mt][nt][2] * d0 + acc[mt][nt][3] * d1;
            }
#pragma unroll
            for (int o = 1; o < 4; o <<= 1) {
                es0 += __shfl_xor_sync(0xffffffffu, es0, o);
                es1 += __shfl_xor_sync(0xffffffffu, es1, o);
                ed0 += __shfl_xor_sync(0xffffffffu, ed0, o);
                ed1 += __shfl_xor_sync(0xffffffffu, ed1, o);
            }
            if (t == 0) {
                int h = (cb + wn) / NCLS;
                int r0 = rb + wm + mt * 16 + g, r1 = r0 + 8;
                if (r0 < Nn) { ES[r0 * 4 + h] = es0; ED[r0 * 4 + h] = ed0; }
                if (r1 < Nn) { ES[r1 * 4 + h] = es1; ED[r1 * 4 + h] = ed1; }
            }
        }
    }
}

// ---------------- agg1: 16 lanes/edge, 2 edges/step (R7 shape), fused ELU+LN ------
__global__ void agg1_kernel(const float* __restrict__ b1, const float* __restrict__ g,
                            const float* __restrict__ bb) {
    int node = (blockIdx.x * blockDim.x + threadIdx.x) >> 5;
    if (node >= Nn) return;
    int lane = threadIdx.x & 31;
    int sub = lane >> 4, m = lane & 15;
    int hm = m >> 2;
    const float4* __restrict__ h4 = (const float4*)g_h1h;  // 16 float4/row

    float edv = g_ed1[node * 4 + hm];
    float pself = __expf(lrelu(g_es1[node * 4 + hm] + edv));

    float acc[8];
    {
        float4 hv = h4[(size_t)node * 16 + m];
        const __half2* hp = (const __half2*)&hv;
        float p0 = (sub == 0) ? pself : 0.f;
#pragma unroll
        for (int i = 0; i < 4; i++) {
            float2 f = __half22float2(hp[i]);
            acc[2 * i] = p0 * f.x;
            acc[2 * i + 1] = p0 * f.y;
        }
    }
    float dl = (sub == 0 && (m & 3) == 0) ? pself : 0.f;

    int deg = min(g_deg[node], CAP);
    const int* __restrict__ cols = g_adj + (size_t)node * CAP;
#pragma unroll 4
    for (int base = 0; base < deg; base += 2) {
        int j = base + sub;
        bool vld = j < deg;
        int sidx = vld ? cols[j] : 0;
        float p = vld ? __expf(lrelu(g_es1[sidx * 4 + hm] + edv)) : 0.f;
        if ((m & 3) == 0) dl += p;
        float4 hv = h4[(size_t)sidx * 16 + m];
        const __half2* hp = (const __half2*)&hv;
#pragma unroll
        for (int i = 0; i < 4; i++) {
            float2 f = __half22float2(hp[i]);
            acc[2 * i] = fmaf(p, f.x, acc[2 * i]);
            acc[2 * i + 1] = fmaf(p, f.y, acc[2 * i + 1]);
        }
    }
#pragma unroll
    for (int i = 0; i < 8; i++) acc[i] += __shfl_xor_sync(0xffffffffu, acc[i], 16);
    dl += __shfl_xor_sync(0xffffffffu, dl, 16);
    float d = __shfl_sync(0xffffffffu, dl, hm * 4);
    float inv = 1.0f / (d + 1e-16f);

    float4 bq0 = *(const float4*)&b1[8 * m];
    float4 bq1 = *(const float4*)&b1[8 * m + 4];
    float bv[8] = {bq0.x, bq0.y, bq0.z, bq0.w, bq1.x, bq1.y, bq1.z, bq1.w};
    float v[8];
    float s = 0.f;
#pragma unroll
    for (int i = 0; i < 8; i++) {
        float x = acc[i] * inv + bv[i];
        v[i] = (x > 0.f) ? x : (__expf(x) - 1.0f);
        s += v[i];
    }
#pragma unroll
    for (int o = 1; o < 16; o <<= 1) s += __shfl_xor_sync(0xffffffffu, s, o);
    float mu = s * (1.0f / 128.0f);
    float vs = 0.f;
#pragma unroll
    for (int i = 0; i < 8; i++) {
        float dd = v[i] - mu;
        vs += dd * dd;
    }
#pragma unroll
    for (int o = 1; o < 16; o <<= 1) vs += __shfl_xor_sync(0xffffffffu, vs, o);
    float rs = rsqrtf(vs * (1.0f / 128.0f) + 1e-5f);
    if (sub == 0) {
        float4 gq0 = *(const float4*)&g[8 * m];
        float4 gq1 = *(const float4*)&g[8 * m + 4];
        float4 cq0 = *(const float4*)&bb[8 * m];
        float4 cq1 = *(const float4*)&bb[8 * m + 4];
        float* __restrict__ on = g_h1a + (size_t)node * D1 + 8 * m;
        *(float4*)&on[0] = make_float4((v[0] - mu) * rs * gq0.x + cq0.x,
                                       (v[1] - mu) * rs * gq0.y + cq0.y,
                                       (v[2] - mu) * rs * gq0.z + cq0.z,
                                       (v[3] - mu) * rs * gq0.w + cq0.w);
        *(float4*)&on[4] = make_float4((v[4] - mu) * rs * gq1.x + cq1.x,
                                       (v[5] - mu) * rs * gq1.y + cq1.y,
                                       (v[6] - mu) * rs * gq1.z + cq1.z,
                                       (v[7] - mu) * rs * gq1.w + cq1.w);
    }
}

// ---------------- agg2: head-aligned permuted layout, 16 lanes/edge ----------------
__global__ void agg2_kernel(const float* __restrict__ b2, const float* __restrict__ g,
                            const float* __restrict__ bb, float* __restrict__ out) {
    __shared__ float stage[8][D2];
    int node = (blockIdx.x * blockDim.x + threadIdx.x) >> 5;
    if (node >= Nn) return;
    int lane = threadIdx.x & 31;
    int sub = lane >> 4, m = lane & 15;
    int h = m >> 2;
    int warp = (threadIdx.x >> 5) & 7;
    const __half2* __restrict__ hp = (const __half2*)g_h2h;  // 80 half2/row, permuted

    float edv = g_ed2[node * 4 + h];
    float pself = __expf(lrelu(g_es2[node * 4 + h] + edv));

    float acc[10];
    {
        float p0 = (sub == 0) ? pself : 0.f;
        const __half2* hr = hp + (size_t)node * 80 + m;
#pragma unroll
        for (int q = 0; q < 5; q++) {
            float2 f = __half22float2(hr[16 * q]);
            acc[2 * q] = p0 * f.x;
            acc[2 * q + 1] = p0 * f.y;
        }
    }
    float dl = (sub == 0) ? pself : 0.f;

    int deg = min(g_deg[node], CAP);
    const int* __restrict__ cols = g_adj + (size_t)node * CAP;
#pragma unroll 4
    for (int base = 0; base < deg; base += 2) {
        int j = base + sub;
        bool vld = j < deg;
        int sidx = vld ? cols[j] : 0;
        float p = vld ? __expf(lrelu(g_es2[sidx * 4 + h] + edv)) : 0.f;
        dl += p;
        const __half2* hr = hp + (size_t)sidx * 80 + m;
#pragma unroll
        for (int q = 0; q < 5; q++) {
            float2 f = __half22float2(hr[16 * q]);
            acc[2 * q] = fmaf(p, f.x, acc[2 * q]);
            acc[2 * q + 1] = fmaf(p, f.y, acc[2 * q + 1]);
        }
    }
#pragma unroll
    for (int i = 0; i < 10; i++) acc[i] += __shfl_xor_sync(0xffffffffu, acc[i], 16);
    dl += __shfl_xor_sync(0xffffffffu, dl, 16);
    float inv = 1.0f / (dl + 1e-16f);

    if (sub == 0) {
        int ubase = h * 20 + (m & 3) * 5;  // logical half2 index base
#pragma unroll
        for (int q = 0; q < 5; q++) {
            int c = 2 * (ubase + q);
            stage[warp][c] = acc[2 * q] * inv;
            stage[warp][c + 1] = acc[2 * q + 1] * inv;
        }
    }
    __syncwarp();

    bool has1 = lane < 8;
    float v0 = 0.f, v1 = 0.f;
#pragma unroll
    for (int hh = 0; hh < 4; hh++) {
        v0 += stage[warp][hh * NCLS + lane];
        if (has1) v1 += stage[warp][hh * NCLS + 32 + lane];
    }
    v0 = 0.25f * v0 + b2[lane];
    if (has1) v1 = 0.25f * v1 + b2[lane + 32];

    float s = wsum(v0 + (has1 ? v1 : 0.f));
    float mu = s * (1.0f / 40.0f);
    float d0 = v0 - mu;
    float d1 = has1 ? (v1 - mu) : 0.f;
    float vs = wsum(d0 * d0 + d1 * d1) * (1.0f / 40.0f);
    float rs = rsqrtf(vs + 1e-5f);
    float y0 = d0 * rs * g[lane] + bb[lane];
    float y1 = has1 ? (d1 * rs * g[lane + 32] + bb[lane + 32]) : -INFINITY;

    float mx = wmax(fmaxf(y0, y1));
    float se = wsum(__expf(y0 - mx) + (has1 ? __expf(y1 - mx) : 0.f));
    float lse = mx + logf(se);
    out[(size_t)node * NCLS + lane] = y0 - lse;
    if (has1) out[(size_t)node * NCLS + lane + 32] = y1 - lse;
}

// ---------------- launch ----------------
extern "C" void kernel_launch(void* const* d_in, const int* in_sizes, int n_in,
                              void* d_out, int out_size) {
    const float* x   = (const float*)d_in[0];
    const int*   ei  = (const int*)d_in[1];
    const float* W1  = (const float*)d_in[2];
    const float* as1 = (const float*)d_in[3];
    const float* ad1 = (const float*)d_in[4];
    const float* b1  = (const float*)d_in[5];
    const float* W2  = (const float*)d_in[6];
    const float* as2 = (const float*)d_in[7];
    const float* ad2 = (const float*)d_in[8];
    const float* b2  = (const float*)d_in[9];
    const float* ln0g = (const float*)d_in[10];
    const float* ln0b = (const float*)d_in[11];
    const float* ln1g = (const float*)d_in[12];
    const float* ln1b = (const float*)d_in[13];
    float* out = (float*)d_out;

    const int* srcp = ei;
    const int* dstp = ei + Ee;

    // Fork CSR build onto a side stream, overlapped with gemm1 (fork/join via events
    // is graph-capture legal). Streams/events are host objects (no device memory);
    // created fresh each call for determinism, intentionally not destroyed (capture-safe).
    cudaStream_t side = 0;
    cudaEvent_t evFork = 0, evJoin = 0;
    bool forked = (cudaStreamCreateWithFlags(&side, cudaStreamNonBlocking) == cudaSuccess) &&
                  (cudaEventCreateWithFlags(&evFork, cudaEventDisableTiming) == cudaSuccess) &&
                  (cudaEventCreateWithFlags(&evJoin, cudaEventDisableTiming) == cudaSuccess);

    if (forked) {
        cudaEventRecord(evFork, 0);
        cudaStreamWaitEvent(side, evFork, 0);
        zero_deg_kernel<<<(Nn + 255) / 256, 256, 0, side>>>();
        fill_kernel<<<(Ee + 255) / 256, 256, 0, side>>>(srcp, dstp);
        cudaEventRecord(evJoin, side);
    } else {
        zero_deg_kernel<<<(Nn + 255) / 256, 256>>>();
        fill_kernel<<<(Ee + 255) / 256, 256>>>(srcp, dstp);
    }

    {
        dim3 grid(1, (Nn + 127) / 128);
        gemm_tc<0><<<grid, 256>>>(x, W1, as1, ad1);
    }
    if (forked) cudaStreamWaitEvent(0, evJoin, 0);
    agg1_kernel<<<(Nn * 32 + 255) / 256, 256>>>(b1, ln0g, ln0b);

    {
        dim3 grid(2, (Nn + 127) / 128);
        gemm_tc<1><<<grid, 256>>>(nullptr, W2, as2, ad2);
    }
    agg2_kernel<<<(Nn * 32 + 255) / 256, 256>>>(b2, ln1g, ln1b, out);
}

// round 11
// speedup vs baseline: 1.3722x; 1.0320x over previous
#include <cuda_runtime.h>
#include <cuda_fp16.h>
#include <math.h>
#include <stdint.h>

#define Nn 50000
#define Ee 800000
#define FIN 256
#define D1 128   // H1*HID
#define D2 160   // H2*NCLS
#define NCLS 40
#define CAP 96   // max in-degree (Poisson(16): P(>=96) ~ 1e-18)

// ---------------- scratch ----------------
__device__ __half g_h1h[(size_t)Nn * D1];   // x @ W1 (fp16)
__device__ float g_h1a[(size_t)Nn * D1];    // post conv1+elu+ln (fp32, gemm2 input)
__device__ __half g_h2h[(size_t)Nn * D2];   // h1a @ W2 (fp16, PERMUTED layout)
__device__ float g_es1[Nn * 4], g_ed1[Nn * 4];
__device__ float g_es2[Nn * 4], g_ed2[Nn * 4];
__device__ int g_deg[Nn];
__device__ int g_adj[(size_t)Nn * CAP];

// Permuted h2 layout: half2 slot s = 16*q + m  (m in [0,16), q in [0,5))
// holds logical channel pair u = (m>>2)*20 + (m&3)*5 + q.

// ---------------- helpers ----------------
__device__ __forceinline__ float wsum(float v) {
#pragma unroll
    for (int o = 16; o > 0; o >>= 1) v += __shfl_xor_sync(0xffffffffu, v, o);
    return v;
}
__device__ __forceinline__ float wmax(float v) {
#pragma unroll
    for (int o = 16; o > 0; o >>= 1) v = fmaxf(v, __shfl_xor_sync(0xffffffffu, v, o));
    return v;
}
__device__ __forceinline__ float lrelu(float x) { return fmaxf(x, 0.2f * x); }
__device__ __forceinline__ void cp16(uint32_t dst, const float* src, int bytes) {
    asm volatile("cp.async.ca.shared.global [%0], [%1], 16, %2;"
                 :: "r"(dst), "l"(src), "r"(bytes));
}

// ---------------- adjacency build ----------------
__global__ void zero_deg_kernel() {
    int i = blockIdx.x * blockDim.x + threadIdx.x;
    if (i < Nn) g_deg[i] = 0;
}
__global__ void fill_kernel(const int* __restrict__ src, const int* __restrict__ dst) {
    int i = blockIdx.x * blockDim.x + threadIdx.x;
    if (i < Ee) {
        int d = dst[i];
        int pos = atomicAdd(&g_deg[d], 1);
        if (pos < CAP) g_adj[(size_t)d * CAP + pos] = src[i];
    }
}

// ---------------- tf32 GEMM, cp.async double-buffered, fp16 out + fused att ------
template <int SEL>
__global__ void __launch_bounds__(256, 2) gemm_tc(const float* __restrict__ Aparam,
                                                  const float* __restrict__ B,
                                                  const float* __restrict__ AS,
                                                  const float* __restrict__ AD) {
    constexpr int K = SEL ? D1 : FIN;
    constexpr int NDIM = SEL ? D2 : D1;
    constexpr int NT = SEL ? 80 : 128;
    constexpr int NTILE = NT / 16;
    constexpr int BPAD = NT + 8;
    constexpr int KC = 16;
    constexpr int NITER = K / KC;
    constexpr int BVEC = (KC * NT) / 4;
    const float* __restrict__ A = SEL ? (const float*)g_h1a : Aparam;
    __half* __restrict__ C = SEL ? g_h2h : g_h1h;
    float* __restrict__ ES = SEL ? g_es2 : g_es1;
    float* __restrict__ ED = SEL ? g_ed2 : g_ed1;

    __shared__ float As[2][128][20];
    __shared__ float Bs[2][KC][BPAD];
    uint32_t asB = (uint32_t)__cvta_generic_to_shared(&As[0][0][0]);
    uint32_t bsB = (uint32_t)__cvta_generic_to_shared(&Bs[0][0][0]);

    int tid = threadIdx.x;
    int lane = tid & 31, wid = tid >> 5;
    int wm = (wid & 3) * 32;
    int wn = (wid >> 2) * (NT / 2);
    int g = lane >> 2, t = lane & 3;
    int rb = blockIdx.y * 128, cb = blockIdx.x * NT;

    float acc[2][NTILE][4];
#pragma unroll
    for (int mt = 0; mt < 2; mt++)
#pragma unroll
        for (int nt = 0; nt < NTILE; nt++)
#pragma unroll
            for (int q = 0; q < 4; q++) acc[mt][nt][q] = 0.f;

    int arow[2], acol[2];
#pragma unroll
    for (int q = 0; q < 2; q++) {
        int idx = tid + q * 256;
        arow[q] = idx >> 2;
        acol[q] = (idx & 3) * 4;
    }
    int brow[2], bcol[2];
    bool bval[2];
#pragma unroll
    for (int q = 0; q < 2; q++) {
        int idx = tid + q * 256;
        bval[q] = idx < BVEC;
        brow[q] = idx / (NT / 4);
        bcol[q] = (idx % (NT / 4)) * 4;
    }

    auto issueTile = [&](int k0, int buf) {
#pragma unroll
        for (int q = 0; q < 2; q++) {
            int r = rb + arow[q];
            bool ok = r < Nn;
            const float* s = A + (size_t)(ok ? r : 0) * K + k0 + acol[q];
            uint32_t d = asB + (((buf * 128 + arow[q]) * 20 + acol[q]) << 2);
            cp16(d, s, ok ? 16 : 0);
        }
#pragma unroll
        for (int q = 0; q < 2; q++) {
            if (bval[q]) {
                const float* s = B + (size_t)(k0 + brow[q]) * NDIM + cb + bcol[q];
                uint32_t d = bsB + (((buf * KC + brow[q]) * BPAD + bcol[q]) << 2);
                cp16(d, s, 16);
            }
        }
        asm volatile("cp.async.commit_group;");
    };

    issueTile(0, 0);

    for (int it = 0; it < NITER; it++) {
        int cur = it & 1;
        if (it + 1 < NITER) {
            issueTile((it + 1) * KC, 1 - cur);
            asm volatile("cp.async.wait_group 1;");
        } else {
            asm volatile("cp.async.wait_group 0;");
        }
        __syncthreads();
#pragma unroll
        for (int ks = 0; ks < 2; ks++) {
            int kk = ks * 8;
            uint32_t afr[2][4];
#pragma unroll
            for (int mt = 0; mt < 2; mt++) {
                int m = wm + mt * 16 + g;
                afr[mt][0] = __float_as_uint(As[cur][m][kk + t]);
                afr[mt][1] = __float_as_uint(As[cur][m + 8][kk + t]);
                afr[mt][2] = __float_as_uint(As[cur][m][kk + t + 4]);
                afr[mt][3] = __float_as_uint(As[cur][m + 8][kk + t + 4]);
            }
#pragma unroll
            for (int nt = 0; nt < NTILE; nt++) {
                uint32_t b0 = __float_as_uint(Bs[cur][kk + t][wn + nt * 8 + g]);
                uint32_t b1 = __float_as_uint(Bs[cur][kk + t + 4][wn + nt * 8 + g]);
#pragma unroll
                for (int mt = 0; mt < 2; mt++) {
                    asm volatile(
                        "mma.sync.aligned.m16n8k8.row.col.f32.tf32.tf32.f32 "
                        "{%0,%1,%2,%3}, {%4,%5,%6,%7}, {%8,%9}, {%0,%1,%2,%3};"
                        : "+f"(acc[mt][nt][0]), "+f"(acc[mt][nt][1]),
                          "+f"(acc[mt][nt][2]), "+f"(acc[mt][nt][3])
                        : "r"(afr[mt][0]), "r"(afr[mt][1]), "r"(afr[mt][2]), "r"(afr[mt][3]),
                          "r"(b0), "r"(b1));
                }
            }
        }
        __syncthreads();
    }

    __half2* __restrict__ C2 = (__half2*)C;
#pragma unroll
    for (int mt = 0; mt < 2; mt++) {
        int r0 = rb + wm + mt * 16 + g;
        int r1 = r0 + 8;
#pragma unroll
        for (int nt = 0; nt < NTILE; nt++) {
            int c = cb + wn + nt * 8 + t * 2;
            size_t sIdx;
            if (SEL == 0) {
                sIdx = c / 2;
            } else {
                int u = c >> 1;
                int h = u / 20;
                int w = u - 20 * h;
                int mq = w / 5;
                int q = w - 5 * mq;
                sIdx = 16 * q + 4 * h + mq;  // permuted slot
            }
            if (r0 < Nn) C2[(size_t)r0 * (NDIM / 2) + sIdx] =
                __floats2half2_rn(acc[mt][nt][0], acc[mt][nt][1]);
            if (r1 < Nn) C2[(size_t)r1 * (NDIM / 2) + sIdx] =
                __floats2half2_rn(acc[mt][nt][2], acc[mt][nt][3]);
        }
    }

    // fused attention coefficients
    if (SEL == 0) {
#pragma unroll
        for (int mt = 0; mt < 2; mt++) {
            float esA0 = 0.f, esA1 = 0.f, esB0 = 0.f, esB1 = 0.f;
            float edA0 = 0.f, edA1 = 0.f, edB0 = 0.f, edB1 = 0.f;
#pragma unroll
            for (int nt = 0; nt < NTILE; nt++) {
                int c = wn + nt * 8 + t * 2;
                float a0 = AS[c], a1 = AS[c + 1];
                float d0 = AD[c], d1 = AD[c + 1];
                float e0 = acc[mt][nt][0] * a0 + acc[mt][nt][1] * a1;
                float e1 = acc[mt][nt][2] * a0 + acc[mt][nt][3] * a1;
                float f0 = acc[mt][nt][0] * d0 + acc[mt][nt][1] * d1;
                float f1 = acc[mt][nt][2] * d0 + acc[mt][nt][3] * d1;
                if (nt < 4) { esA0 += e0; esA1 += e1; edA0 += f0; edA1 += f1; }
                else        { esB0 += e0; esB1 += e1; edB0 += f0; edB1 += f1; }
            }
#pragma unroll
            for (int o = 1; o < 4; o <<= 1) {
                esA0 += __shfl_xor_sync(0xffffffffu, esA0, o);
                esA1 += __shfl_xor_sync(0xffffffffu, esA1, o);
                esB0 += __shfl_xor_sync(0xffffffffu, esB0, o);
                esB1 += __shfl_xor_sync(0xffffffffu, esB1, o);
                edA0 += __shfl_xor_sync(0xffffffffu, edA0, o);
                edA1 += __shfl_xor_sync(0xffffffffu, edA1, o);
                edB0 += __shfl_xor_sync(0xffffffffu, edB0, o);
                edB1 += __shfl_xor_sync(0xffffffffu, edB1, o);
            }
            if (t == 0) {
                int hA = wn >> 5;
                int r0 = rb + wm + mt * 16 + g, r1 = r0 + 8;
                if (r0 < Nn) {
                    ES[r0 * 4 + hA] = esA0; ES[r0 * 4 + hA + 1] = esB0;
                    ED[r0 * 4 + hA] = edA0; ED[r0 * 4 + hA + 1] = edB0;
                }
                if (r1 < Nn) {
                    ES[r1 * 4 + hA] = esA1; ES[r1 * 4 + hA + 1] = esB1;
                    ED[r1 * 4 + hA] = edA1; ED[r1 * 4 + hA + 1] = edB1;
                }
            }
        }
    } else {
#pragma unroll
        for (int mt = 0; mt < 2; mt++) {
            float es0 = 0.f, es1 = 0.f, ed0 = 0.f, ed1 = 0.f;
#pragma unroll
            for (int nt = 0; nt < NTILE; nt++) {
                int c = cb + wn + nt * 8 + t * 2;
                float a0 = AS[c], a1 = AS[c + 1];
                float d0 = AD[c], d1 = AD[c + 1];
                es0 += acc[mt][nt][0] * a0 + acc[mt][nt][1] * a1;
                es1 += acc[mt][nt][2] * a0 + acc[mt][nt][3] * a1;
                ed0 += acc[mt][nt][0] * d0 + acc[mt][nt][1] * d1;
                ed1 += acc[mt][nt][2] * d0 + acc[mt][nt][3] * d1;
            }
#pragma unroll
            for (int o = 1; o < 4; o <<= 1) {
                es0 += __shfl_xor_sync(0xffffffffu, es0, o);
                es1 += __shfl_xor_sync(0xffffffffu, es1, o);
                ed0 += __shfl_xor_sync(0xffffffffu, ed0, o);
                ed1 += __shfl_xor_sync(0xffffffffu, ed1, o);
            }
            if (t == 0) {
                int h = (cb + wn) / NCLS;
                int r0 = rb + wm + mt * 16 + g, r1 = r0 + 8;
                if (r0 < Nn) { ES[r0 * 4 + h] = es0; ED[r0 * 4 + h] = ed0; }
                if (r1 < Nn) { ES[r1 * 4 + h] = es1; ED[r1 * 4 + h] = ed1; }
            }
        }
    }
}

// ---------------- agg1: pipelined, all-lane denominators, fused ELU+LN ----------
__global__ void agg1_kernel(const float* __restrict__ b1, const float* __restrict__ g,
                            const float* __restrict__ bb) {
    int node = (blockIdx.x * blockDim.x + threadIdx.x) >> 5;
    if (node >= Nn) return;
    int lane = threadIdx.x & 31;
    int sub = lane >> 4, m = lane & 15;
    int hm = m >> 2;
    const float4* __restrict__ h4 = (const float4*)g_h1h;  // 16 float4/row

    float edv = g_ed1[node * 4 + hm];
    float pself = __expf(lrelu(g_es1[node * 4 + hm] + edv));

    float acc[8];
    {
        float4 hv = h4[(size_t)node * 16 + m];
        const __half2* hp = (const __half2*)&hv;
        float p0 = (sub == 0) ? pself : 0.f;
#pragma unroll
        for (int i = 0; i < 4; i++) {
            float2 f = __half22float2(hp[i]);
            acc[2 * i] = p0 * f.x;
            acc[2 * i + 1] = p0 * f.y;
        }
    }
    float dl = (sub == 0) ? pself : 0.f;

    int deg = min(g_deg[node], CAP);
    const int* __restrict__ cols = g_adj + (size_t)node * CAP;

    // prologue prefetch
    bool vld = sub < deg;
    int sidx = vld ? cols[sub] : 0;
    float esv = g_es1[sidx * 4 + hm];

#pragma unroll 2
    for (int base = 0; base < deg; base += 2) {
        bool cv = vld;
        int cs = sidx;
        float ce = esv;
        // prefetch next step
        int jn = base + 2 + sub;
        vld = jn < deg;
        sidx = vld ? cols[jn] : 0;
        esv = g_es1[sidx * 4 + hm];
        // current step
        float p = cv ? __expf(lrelu(ce + edv)) : 0.f;
        dl += p;
        float4 hv = h4[(size_t)cs * 16 + m];
        const __half2* hp = (const __half2*)&hv;
#pragma unroll
        for (int i = 0; i < 4; i++) {
            float2 f = __half22float2(hp[i]);
            acc[2 * i] = fmaf(p, f.x, acc[2 * i]);
            acc[2 * i + 1] = fmaf(p, f.y, acc[2 * i + 1]);
        }
    }
#pragma unroll
    for (int i = 0; i < 8; i++) acc[i] += __shfl_xor_sync(0xffffffffu, acc[i], 16);
    dl += __shfl_xor_sync(0xffffffffu, dl, 16);
    float inv = 1.0f / (dl + 1e-16f);

    float4 bq0 = *(const float4*)&b1[8 * m];
    float4 bq1 = *(const float4*)&b1[8 * m + 4];
    float bv[8] = {bq0.x, bq0.y, bq0.z, bq0.w, bq1.x, bq1.y, bq1.z, bq1.w};
    float v[8];
    float s = 0.f;
#pragma unroll
    for (int i = 0; i < 8; i++) {
        float x = acc[i] * inv + bv[i];
        v[i] = (x > 0.f) ? x : (__expf(x) - 1.0f);
        s += v[i];
    }
#pragma unroll
    for (int o = 1; o < 16; o <<= 1) s += __shfl_xor_sync(0xffffffffu, s, o);
    float mu = s * (1.0f / 128.0f);
    float vs = 0.f;
#pragma unroll
    for (int i = 0; i < 8; i++) {
        float dd = v[i] - mu;
        vs += dd * dd;
    }
#pragma unroll
    for (int o = 1; o < 16; o <<= 1) vs += __shfl_xor_sync(0xffffffffu, vs, o);
    float rs = rsqrtf(vs * (1.0f / 128.0f) + 1e-5f);
    if (sub == 0) {
        float4 gq0 = *(const float4*)&g[8 * m];
        float4 gq1 = *(const float4*)&g[8 * m + 4];
        float4 cq0 = *(const float4*)&bb[8 * m];
        float4 cq1 = *(const float4*)&bb[8 * m + 4];
        float* __restrict__ on = g_h1a + (size_t)node * D1 + 8 * m;
        *(float4*)&on[0] = make_float4((v[0] - mu) * rs * gq0.x + cq0.x,
                                       (v[1] - mu) * rs * gq0.y + cq0.y,
                                       (v[2] - mu) * rs * gq0.z + cq0.z,
                                       (v[3] - mu) * rs * gq0.w + cq0.w);
        *(float4*)&on[4] = make_float4((v[4] - mu) * rs * gq1.x + cq1.x,
                                       (v[5] - mu) * rs * gq1.y + cq1.y,
                                       (v[6] - mu) * rs * gq1.z + cq1.z,
                                       (v[7] - mu) * rs * gq1.w + cq1.w);
    }
}

// ---------------- agg2: pipelined, head-aligned permuted layout ----------------
__global__ void agg2_kernel(const float* __restrict__ b2, const float* __restrict__ g,
                            const float* __restrict__ bb, float* __restrict__ out) {
    __shared__ float stage[8][D2];
    int node = (blockIdx.x * blockDim.x + threadIdx.x) >> 5;
    if (node >= Nn) return;
    int lane = threadIdx.x & 31;
    int sub = lane >> 4, m = lane & 15;
    int h = m >> 2;
    int warp = (threadIdx.x >> 5) & 7;
    const __half2* __restrict__ hp = (const __half2*)g_h2h;  // 80 half2/row, permuted

    float edv = g_ed2[node * 4 + h];
    float pself = __expf(lrelu(g_es2[node * 4 + h] + edv));

    float acc[10];
    {
        float p0 = (sub == 0) ? pself : 0.f;
        const __half2* hr = hp + (size_t)node * 80 + m;
#pragma unroll
        for (int q = 0; q < 5; q++) {
            float2 f = __half22float2(hr[16 * q]);
            acc[2 * q] = p0 * f.x;
            acc[2 * q + 1] = p0 * f.y;
        }
    }
    float dl = (sub == 0) ? pself : 0.f;

    int deg = min(g_deg[node], CAP);
    const int* __restrict__ cols = g_adj + (size_t)node * CAP;

    bool vld = sub < deg;
    int sidx = vld ? cols[sub] : 0;
    float esv = g_es2[sidx * 4 + h];

#pragma unroll 2
    for (int base = 0; base < deg; base += 2) {
        bool cv = vld;
        int cs = sidx;
        float ce = esv;
        int jn = base + 2 + sub;
        vld = jn < deg;
        sidx = vld ? cols[jn] : 0;
        esv = g_es2[sidx * 4 + h];
        float p = cv ? __expf(lrelu(ce + edv)) : 0.f;
        dl += p;
        const __half2* hr = hp + (size_t)cs * 80 + m;
#pragma unroll
        for (int q = 0; q < 5; q++) {
            float2 f = __half22float2(hr[16 * q]);
            acc[2 * q] = fmaf(p, f.x, acc[2 * q]);
            acc[2 * q + 1] = fmaf(p, f.y, acc[2 * q + 1]);
        }
    }
#pragma unroll
    for (int i = 0; i < 10; i++) acc[i] += __shfl_xor_sync(0xffffffffu, acc[i], 16);
    dl += __shfl_xor_sync(0xffffffffu, dl, 16);
    float inv = 1.0f / (dl + 1e-16f);

    if (sub == 0) {
        int ubase = h * 20 + (m & 3) * 5;
#pragma unroll
        for (int q = 0; q < 5; q++) {
            int c = 2 * (ubase + q);
            stage[warp][c] = acc[2 * q] * inv;
            stage[warp][c + 1] = acc[2 * q + 1] * inv;
        }
    }
    __syncwarp();

    bool has1 = lane < 8;
    float v0 = 0.f, v1 = 0.f;
#pragma unroll
    for (int hh = 0; hh < 4; hh++) {
        v0 += stage[warp][hh * NCLS + lane];
        if (has1) v1 += stage[warp][hh * NCLS + 32 + lane];
    }
    v0 = 0.25f * v0 + b2[lane];
    if (has1) v1 = 0.25f * v1 + b2[lane + 32];

    float s = wsum(v0 + (has1 ? v1 : 0.f));
    float mu = s * (1.0f / 40.0f);
    float d0 = v0 - mu;
    float d1 = has1 ? (v1 - mu) : 0.f;
    float vs = wsum(d0 * d0 + d1 * d1) * (1.0f / 40.0f);
    float rs = rsqrtf(vs + 1e-5f);
    float y0 = d0 * rs * g[lane] + bb[lane];
    float y1 = has1 ? (d1 * rs * g[lane + 32] + bb[lane + 32]) : -INFINITY;

    float mx = wmax(fmaxf(y0, y1));
    float se = wsum(__expf(y0 - mx) + (has1 ? __expf(y1 - mx) : 0.f));
    float lse = mx + logf(se);
    out[(size_t)node * NCLS + lane] = y0 - lse;
    if (has1) out[(size_t)node * NCLS + lane + 32] = y1 - lse;
}

// ---------------- launch ----------------
extern "C" void kernel_launch(void* const* d_in, const int* in_sizes, int n_in,
                              void* d_out, int out_size) {
    const float* x   = (const float*)d_in[0];
    const int*   ei  = (const int*)d_in[1];
    const float* W1  = (const float*)d_in[2];
    const float* as1 = (const float*)d_in[3];
    const float* ad1 = (const float*)d_in[4];
    const float* b1  = (const float*)d_in[5];
    const float* W2  = (const float*)d_in[6];
    const float* as2 = (const float*)d_in[7];
    const float* ad2 = (const float*)d_in[8];
    const float* b2  = (const float*)d_in[9];
    const float* ln0g = (const float*)d_in[10];
    const float* ln0b = (const float*)d_in[11];
    const float* ln1g = (const float*)d_in[12];
    const float* ln1b = (const float*)d_in[13];
    float* out = (float*)d_out;

    const int* srcp = ei;
    const int* dstp = ei + Ee;

    // Fork CSR build onto a side stream, overlapped with gemm1.
    cudaStream_t side = 0;
    cudaEvent_t evFork = 0, evJoin = 0;
    bool forked = (cudaStreamCreateWithFlags(&side, cudaStreamNonBlocking) == cudaSuccess) &&
                  (cudaEventCreateWithFlags(&evFork, cudaEventDisableTiming) == cudaSuccess) &&
                  (cudaEventCreateWithFlags(&evJoin, cudaEventDisableTiming) == cudaSuccess);

    if (forked) {
        cudaEventRecord(evFork, 0);
        cudaStreamWaitEvent(side, evFork, 0);
        zero_deg_kernel<<<(Nn + 255) / 256, 256, 0, side>>>();
        fill_kernel<<<(Ee + 255) / 256, 256, 0, side>>>(srcp, dstp);
        cudaEventRecord(evJoin, side);
    } else {
        zero_deg_kernel<<<(Nn + 255) / 256, 256>>>();
        fill_kernel<<<(Ee + 255) / 256, 256>>>(srcp, dstp);
    }

    {
        dim3 grid(1, (Nn + 127) / 128);
        gemm_tc<0><<<grid, 256>>>(x, W1, as1, ad1);
    }
    if (forked) cudaStreamWaitEvent(0, evJoin, 0);
    agg1_kernel<<<(Nn * 32 + 255) / 256, 256>>>(b1, ln0g, ln0b);

    {
        dim3 grid(2, (Nn + 127) / 128);
        gemm_tc<1><<<grid, 256>>>(nullptr, W2, as2, ad2);
    }
    agg2_kernel<<<(Nn * 32 + 255) / 256, 256>>>(b2, ln1g, ln1b, out);
}

// round 12
// speedup vs baseline: 1.3967x; 1.0178x over previous
#include <cuda_runtime.h>
#include <cuda_fp16.h>
#include <math.h>
#include <stdint.h>

#define Nn 50000
#define Ee 800000
#define FIN 256
#define D1 128   // H1*HID
#define D2 160   // H2*NCLS
#define NCLS 40
#define CAP 96   // max in-degree (Poisson(16): P(>=96) ~ 1e-18)

// ---------------- scratch (row Nn = sentinel row, stays zero) ----------------
__device__ __half g_h1h[(size_t)(Nn + 1) * D1];   // x @ W1 (fp16)
__device__ float g_h1a[(size_t)Nn * D1];          // post conv1+elu+ln (fp32)
__device__ __half g_h2h[(size_t)(Nn + 1) * D2];   // h1a @ W2 (fp16, PERMUTED)
__device__ float g_es1[(Nn + 1) * 4], g_ed1[Nn * 4];
__device__ float g_es2[(Nn + 1) * 4], g_ed2[Nn * 4];
__device__ int g_deg[Nn];
__device__ int g_adj[(size_t)Nn * CAP];

// Permuted h2 layout: half2 slot s = 16*q + m  (m in [0,16), q in [0,5))
// holds logical channel pair u = (m>>2)*20 + (m&3)*5 + q.

// ---------------- helpers ----------------
__device__ __forceinline__ float wsum(float v) {
#pragma unroll
    for (int o = 16; o > 0; o >>= 1) v += __shfl_xor_sync(0xffffffffu, v, o);
    return v;
}
__device__ __forceinline__ float wmax(float v) {
#pragma unroll
    for (int o = 16; o > 0; o >>= 1) v = fmaxf(v, __shfl_xor_sync(0xffffffffu, v, o));
    return v;
}
__device__ __forceinline__ float lrelu(float x) { return fmaxf(x, 0.2f * x); }
__device__ __forceinline__ void cp16(uint32_t dst, const float* src, int bytes) {
    asm volatile("cp.async.ca.shared.global [%0], [%1], 16, %2;"
                 :: "r"(dst), "l"(src), "r"(bytes));
}

// ---------------- adjacency build ----------------
__global__ void zero_deg_kernel() {
    int i = blockIdx.x * blockDim.x + threadIdx.x;
    if (i < Nn) g_deg[i] = 0;
}
__global__ void fill_kernel(const int* __restrict__ src, const int* __restrict__ dst) {
    int i = blockIdx.x * blockDim.x + threadIdx.x;
    if (i < Ee) {
        int d = dst[i];
        int pos = atomicAdd(&g_deg[d], 1);
        if (pos < CAP - 1) g_adj[(size_t)d * CAP + pos] = src[i];
    }
}
// write one sentinel per adjacency list + the sentinel es rows
__global__ void pad_kernel() {
    int i = blockIdx.x * blockDim.x + threadIdx.x;
    if (i < Nn) {
        int d = min(g_deg[i], CAP - 1);
        g_adj[(size_t)i * CAP + d] = Nn;
    }
    if (i < 4) {
        g_es1[Nn * 4 + i] = -1e30f;
        g_es2[Nn * 4 + i] = -1e30f;
    }
}

// ---------------- tf32 GEMM, cp.async double-buffered, fp16 out + fused att ------
template <int SEL>
__global__ void __launch_bounds__(256, 2) gemm_tc(const float* __restrict__ Aparam,
                                                  const float* __restrict__ B,
                                                  const float* __restrict__ AS,
                                                  const float* __restrict__ AD) {
    constexpr int K = SEL ? D1 : FIN;
    constexpr int NDIM = SEL ? D2 : D1;
    constexpr int NT = SEL ? 80 : 128;
    constexpr int NTILE = NT / 16;
    constexpr int BPAD = NT + 8;
    constexpr int KC = 16;
    constexpr int NITER = K / KC;
    constexpr int BVEC = (KC * NT) / 4;
    const float* __restrict__ A = SEL ? (const float*)g_h1a : Aparam;
    __half* __restrict__ C = SEL ? g_h2h : g_h1h;
    float* __restrict__ ES = SEL ? g_es2 : g_es1;
    float* __restrict__ ED = SEL ? g_ed2 : g_ed1;

    __shared__ float As[2][128][20];
    __shared__ float Bs[2][KC][BPAD];
    uint32_t asB = (uint32_t)__cvta_generic_to_shared(&As[0][0][0]);
    uint32_t bsB = (uint32_t)__cvta_generic_to_shared(&Bs[0][0][0]);

    int tid = threadIdx.x;
    int lane = tid & 31, wid = tid >> 5;
    int wm = (wid & 3) * 32;
    int wn = (wid >> 2) * (NT / 2);
    int g = lane >> 2, t = lane & 3;
    int rb = blockIdx.y * 128, cb = blockIdx.x * NT;

    float acc[2][NTILE][4];
#pragma unroll
    for (int mt = 0; mt < 2; mt++)
#pragma unroll
        for (int nt = 0; nt < NTILE; nt++)
#pragma unroll
            for (int q = 0; q < 4; q++) acc[mt][nt][q] = 0.f;

    int arow[2], acol[2];
#pragma unroll
    for (int q = 0; q < 2; q++) {
        int idx = tid + q * 256;
        arow[q] = idx >> 2;
        acol[q] = (idx & 3) * 4;
    }
    int brow[2], bcol[2];
    bool bval[2];
#pragma unroll
    for (int q = 0; q < 2; q++) {
        int idx = tid + q * 256;
        bval[q] = idx < BVEC;
        brow[q] = idx / (NT / 4);
        bcol[q] = (idx % (NT / 4)) * 4;
    }

    auto issueTile = [&](int k0, int buf) {
#pragma unroll
        for (int q = 0; q < 2; q++) {
            int r = rb + arow[q];
            bool ok = r < Nn;
            const float* s = A + (size_t)(ok ? r : 0) * K + k0 + acol[q];
            uint32_t d = asB + (((buf * 128 + arow[q]) * 20 + acol[q]) << 2);
            cp16(d, s, ok ? 16 : 0);
        }
#pragma unroll
        for (int q = 0; q < 2; q++) {
            if (bval[q]) {
                const float* s = B + (size_t)(k0 + brow[q]) * NDIM + cb + bcol[q];
                uint32_t d = bsB + (((buf * KC + brow[q]) * BPAD + bcol[q]) << 2);
                cp16(d, s, 16);
            }
        }
        asm volatile("cp.async.commit_group;");
    };

    issueTile(0, 0);

    for (int it = 0; it < NITER; it++) {
        int cur = it & 1;
        if (it + 1 < NITER) {
            issueTile((it + 1) * KC, 1 - cur);
            asm volatile("cp.async.wait_group 1;");
        } else {
            asm volatile("cp.async.wait_group 0;");
        }
        __syncthreads();
#pragma unroll
        for (int ks = 0; ks < 2; ks++) {
            int kk = ks * 8;
            uint32_t afr[2][4];
#pragma unroll
            for (int mt = 0; mt < 2; mt++) {
                int m = wm + mt * 16 + g;
                afr[mt][0] = __float_as_uint(As[cur][m][kk + t]);
                afr[mt][1] = __float_as_uint(As[cur][m + 8][kk + t]);
                afr[mt][2] = __float_as_uint(As[cur][m][kk + t + 4]);
                afr[mt][3] = __float_as_uint(As[cur][m + 8][kk + t + 4]);
            }
#pragma unroll
            for (int nt = 0; nt < NTILE; nt++) {
                uint32_t b0 = __float_as_uint(Bs[cur][kk + t][wn + nt * 8 + g]);
                uint32_t b1 = __float_as_uint(Bs[cur][kk + t + 4][wn + nt * 8 + g]);
#pragma unroll
                for (int mt = 0; mt < 2; mt++) {
                    asm volatile(
                        "mma.sync.aligned.m16n8k8.row.col.f32.tf32.tf32.f32 "
                        "{%0,%1,%2,%3}, {%4,%5,%6,%7}, {%8,%9}, {%0,%1,%2,%3};"
                        : "+f"(acc[mt][nt][0]), "+f"(acc[mt][nt][1]),
                          "+f"(acc[mt][nt][2]), "+f"(acc[mt][nt][3])
                        : "r"(afr[mt][0]), "r"(afr[mt][1]), "r"(afr[mt][2]), "r"(afr[mt][3]),
                          "r"(b0), "r"(b1));
                }
            }
        }
        __syncthreads();
    }

    __half2* __restrict__ C2 = (__half2*)C;
#pragma unroll
    for (int mt = 0; mt < 2; mt++) {
        int r0 = rb + wm + mt * 16 + g;
        int r1 = r0 + 8;
#pragma unroll
        for (int nt = 0; nt < NTILE; nt++) {
            int c = cb + wn + nt * 8 + t * 2;
            size_t sIdx;
            if (SEL == 0) {
                sIdx = c / 2;
            } else {
                int u = c >> 1;
                int h = u / 20;
                int w = u - 20 * h;
                int mq = w / 5;
                int q = w - 5 * mq;
                sIdx = 16 * q + 4 * h + mq;  // permuted slot
            }
            if (r0 < Nn) C2[(size_t)r0 * (NDIM / 2) + sIdx] =
                __floats2half2_rn(acc[mt][nt][0], acc[mt][nt][1]);
            if (r1 < Nn) C2[(size_t)r1 * (NDIM / 2) + sIdx] =
                __floats2half2_rn(acc[mt][nt][2], acc[mt][nt][3]);
        }
    }

    // fused attention coefficients
    if (SEL == 0) {
#pragma unroll
        for (int mt = 0; mt < 2; mt++) {
            float esA0 = 0.f, esA1 = 0.f, esB0 = 0.f, esB1 = 0.f;
            float edA0 = 0.f, edA1 = 0.f, edB0 = 0.f, edB1 = 0.f;
#pragma unroll
            for (int nt = 0; nt < NTILE; nt++) {
                int c = wn + nt * 8 + t * 2;
                float a0 = AS[c], a1 = AS[c + 1];
                float d0 = AD[c], d1 = AD[c + 1];
                float e0 = acc[mt][nt][0] * a0 + acc[mt][nt][1] * a1;
                float e1 = acc[mt][nt][2] * a0 + acc[mt][nt][3] * a1;
                float f0 = acc[mt][nt][0] * d0 + acc[mt][nt][1] * d1;
                float f1 = acc[mt][nt][2] * d0 + acc[mt][nt][3] * d1;
                if (nt < 4) { esA0 += e0; esA1 += e1; edA0 += f0; edA1 += f1; }
                else        { esB0 += e0; esB1 += e1; edB0 += f0; edB1 += f1; }
            }
#pragma unroll
            for (int o = 1; o < 4; o <<= 1) {
                esA0 += __shfl_xor_sync(0xffffffffu, esA0, o);
                esA1 += __shfl_xor_sync(0xffffffffu, esA1, o);
                esB0 += __shfl_xor_sync(0xffffffffu, esB0, o);
                esB1 += __shfl_xor_sync(0xffffffffu, esB1, o);
                edA0 += __shfl_xor_sync(0xffffffffu, edA0, o);
                edA1 += __shfl_xor_sync(0xffffffffu, edA1, o);
                edB0 += __shfl_xor_sync(0xffffffffu, edB0, o);
                edB1 += __shfl_xor_sync(0xffffffffu, edB1, o);
            }
            if (t == 0) {
                int hA = wn >> 5;
                int r0 = rb + wm + mt * 16 + g, r1 = r0 + 8;
                if (r0 < Nn) {
                    ES[r0 * 4 + hA] = esA0; ES[r0 * 4 + hA + 1] = esB0;
                    ED[r0 * 4 + hA] = edA0; ED[r0 * 4 + hA + 1] = edB0;
                }
                if (r1 < Nn) {
                    ES[r1 * 4 + hA] = esA1; ES[r1 * 4 + hA + 1] = esB1;
                    ED[r1 * 4 + hA] = edA1; ED[r1 * 4 + hA + 1] = edB1;
                }
            }
        }
    } else {
#pragma unroll
        for (int mt = 0; mt < 2; mt++) {
            float es0 = 0.f, es1 = 0.f, ed0 = 0.f, ed1 = 0.f;
#pragma unroll
            for (int nt = 0; nt < NTILE; nt++) {
                int c = cb + wn + nt * 8 + t * 2;
                float a0 = AS[c], a1 = AS[c + 1];
                float d0 = AD[c], d1 = AD[c + 1];
                es0 += acc[mt][nt][0] * a0 + acc[mt][nt][1] * a1;
                es1 += acc[mt][nt][2] * a0 + acc[mt][nt][3] * a1;
                ed0 += acc[mt][nt][0] * d0 + acc[mt][nt][1] * d1;
                ed1 += acc[mt][nt][2] * d0 + acc[mt][nt][3] * d1;
            }
#pragma unroll
            for (int o = 1; o < 4; o <<= 1) {
                es0 += __shfl_xor_sync(0xffffffffu, es0, o);
                es1 += __shfl_xor_sync(0xffffffffu, es1, o);
                ed0 += __shfl_xor_sync(0xffffffffu, ed0, o);
                ed1 += __shfl_xor_sync(0xffffffffu, ed1, o);
            }
            if (t == 0) {
                int h = (cb + wn) / NCLS;
                int r0 = rb + wm + mt * 16 + g, r1 = r0 + 8;
                if (r0 < Nn) { ES[r0 * 4 + h] = es0; ED[r0 * 4 + h] = ed0; }
                if (r1 < Nn) { ES[r1 * 4 + h] = es1; ED[r1 * 4 + h] = ed1; }
            }
        }
    }
}

// ---------------- agg1: sentinel-padded, unpredicated inner loop ----------------
__global__ void agg1_kernel(const float* __restrict__ b1, const float* __restrict__ g,
                            const float* __restrict__ bb) {
    int node = (blockIdx.x * blockDim.x + threadIdx.x) >> 5;
    if (node >= Nn) return;
    int lane = threadIdx.x & 31;
    int sub = lane >> 4, m = lane & 15;
    int hm = m >> 2;
    const float4* __restrict__ h4 = (const float4*)g_h1h;  // 16 float4/row

    float edv = g_ed1[node * 4 + hm];
    float pself = __expf(lrelu(g_es1[node * 4 + hm] + edv));

    float acc[8];
    {
        float4 hv = h4[(size_t)node * 16 + m];
        const __half2* hp = (const __half2*)&hv;
        float p0 = (sub == 0) ? pself : 0.f;
#pragma unroll
        for (int i = 0; i < 4; i++) {
            float2 f = __half22float2(hp[i]);
            acc[2 * i] = p0 * f.x;
            acc[2 * i + 1] = p0 * f.y;
        }
    }
    float dl = (sub == 0) ? pself : 0.f;

    int deg = min(g_deg[node], CAP - 1);
    const int* __restrict__ cols = g_adj + (size_t)node * CAP;
#pragma unroll 4
    for (int base = 0; base < deg; base += 2) {
        int sidx = cols[base + sub];                 // sentinel-safe at base+sub == deg
        float p = __expf(lrelu(g_es1[sidx * 4 + hm] + edv));
        dl += p;
        float4 hv = h4[(size_t)sidx * 16 + m];
        const __half2* hp = (const __half2*)&hv;
#pragma unroll
        for (int i = 0; i < 4; i++) {
            float2 f = __half22float2(hp[i]);
            acc[2 * i] = fmaf(p, f.x, acc[2 * i]);
            acc[2 * i + 1] = fmaf(p, f.y, acc[2 * i + 1]);
        }
    }
#pragma unroll
    for (int i = 0; i < 8; i++) acc[i] += __shfl_xor_sync(0xffffffffu, acc[i], 16);
    dl += __shfl_xor_sync(0xffffffffu, dl, 16);
    float inv = 1.0f / (dl + 1e-16f);

    float4 bq0 = *(const float4*)&b1[8 * m];
    float4 bq1 = *(const float4*)&b1[8 * m + 4];
    float bv[8] = {bq0.x, bq0.y, bq0.z, bq0.w, bq1.x, bq1.y, bq1.z, bq1.w};
    float v[8];
    float s = 0.f;
#pragma unroll
    for (int i = 0; i < 8; i++) {
        float x = acc[i] * inv + bv[i];
        v[i] = (x > 0.f) ? x : (__expf(x) - 1.0f);
        s += v[i];
    }
#pragma unroll
    for (int o = 1; o < 16; o <<= 1) s += __shfl_xor_sync(0xffffffffu, s, o);
    float mu = s * (1.0f / 128.0f);
    float vs = 0.f;
#pragma unroll
    for (int i = 0; i < 8; i++) {
        float dd = v[i] - mu;
        vs += dd * dd;
    }
#pragma unroll
    for (int o = 1; o < 16; o <<= 1) vs += __shfl_xor_sync(0xffffffffu, vs, o);
    float rs = rsqrtf(vs * (1.0f / 128.0f) + 1e-5f);
    if (sub == 0) {
        float4 gq0 = *(const float4*)&g[8 * m];
        float4 gq1 = *(const float4*)&g[8 * m + 4];
        float4 cq0 = *(const float4*)&bb[8 * m];
        float4 cq1 = *(const float4*)&bb[8 * m + 4];
        float* __restrict__ on = g_h1a + (size_t)node * D1 + 8 * m;
        *(float4*)&on[0] = make_float4((v[0] - mu) * rs * gq0.x + cq0.x,
                                       (v[1] - mu) * rs * gq0.y + cq0.y,
                                       (v[2] - mu) * rs * gq0.z + cq0.z,
                                       (v[3] - mu) * rs * gq0.w + cq0.w);
        *(float4*)&on[4] = make_float4((v[4] - mu) * rs * gq1.x + cq1.x,
                                       (v[5] - mu) * rs * gq1.y + cq1.y,
                                       (v[6] - mu) * rs * gq1.z + cq1.z,
                                       (v[7] - mu) * rs * gq1.w + cq1.w);
    }
}

// ---------------- agg2: sentinel-padded, permuted layout ----------------
__global__ void agg2_kernel(const float* __restrict__ b2, const float* __restrict__ g,
                            const float* __restrict__ bb, float* __restrict__ out) {
    __shared__ float stage[8][D2];
    int node = (blockIdx.x * blockDim.x + threadIdx.x) >> 5;
    if (node >= Nn) return;
    int lane = threadIdx.x & 31;
    int sub = lane >> 4, m = lane & 15;
    int h = m >> 2;
    int warp = (threadIdx.x >> 5) & 7;
    const __half2* __restrict__ hp = (const __half2*)g_h2h;  // 80 half2/row, permuted

    float edv = g_ed2[node * 4 + h];
    float pself = __expf(lrelu(g_es2[node * 4 + h] + edv));

    float acc[10];
    {
        float p0 = (sub == 0) ? pself : 0.f;
        const __half2* hr = hp + (size_t)node * 80 + m;
#pragma unroll
        for (int q = 0; q < 5; q++) {
            float2 f = __half22float2(hr[16 * q]);
            acc[2 * q] = p0 * f.x;
            acc[2 * q + 1] = p0 * f.y;
        }
    }
    float dl = (sub == 0) ? pself : 0.f;

    int deg = min(g_deg[node], CAP - 1);
    const int* __restrict__ cols = g_adj + (size_t)node * CAP;
#pragma unroll 4
    for (int base = 0; base < deg; base += 2) {
        int sidx = cols[base + sub];
        float p = __expf(lrelu(g_es2[sidx * 4 + h] + edv));
        dl += p;
        const __half2* hr = hp + (size_t)sidx * 80 + m;
#pragma unroll
        for (int q = 0; q < 5; q++) {
            float2 f = __half22float2(hr[16 * q]);
            acc[2 * q] = fmaf(p, f.x, acc[2 * q]);
            acc[2 * q + 1] = fmaf(p, f.y, acc[2 * q + 1]);
        }
    }
#pragma unroll
    for (int i = 0; i < 10; i++) acc[i] += __shfl_xor_sync(0xffffffffu, acc[i], 16);
    dl += __shfl_xor_sync(0xffffffffu, dl, 16);
    float inv = 1.0f / (dl + 1e-16f);

    if (sub == 0) {
        int ubase = h * 20 + (m & 3) * 5;
#pragma unroll
        for (int q = 0; q < 5; q++) {
            int c = 2 * (ubase + q);
            stage[warp][c] = acc[2 * q] * inv;
            stage[warp][c + 1] = acc[2 * q + 1] * inv;
        }
    }
    __syncwarp();

    bool has1 = lane < 8;
    float v0 = 0.f, v1 = 0.f;
#pragma unroll
    for (int hh = 0; hh < 4; hh++) {
        v0 += stage[warp][hh * NCLS + lane];
        if (has1) v1 += stage[warp][hh * NCLS + 32 + lane];
    }
    v0 = 0.25f * v0 + b2[lane];
    if (has1) v1 = 0.25f * v1 + b2[lane + 32];

    float s = wsum(v0 + (has1 ? v1 : 0.f));
    float mu = s * (1.0f / 40.0f);
    float d0 = v0 - mu;
    float d1 = has1 ? (v1 - mu) : 0.f;
    float vs = wsum(d0 * d0 + d1 * d1) * (1.0f / 40.0f);
    float rs = rsqrtf(vs + 1e-5f);
    float y0 = d0 * rs * g[lane] + bb[lane];
    float y1 = has1 ? (d1 * rs * g[lane + 32] + bb[lane + 32]) : -INFINITY;

    float mx = wmax(fmaxf(y0, y1));
    float se = wsum(__expf(y0 - mx) + (has1 ? __expf(y1 - mx) : 0.f));
    float lse = mx + logf(se);
    out[(size_t)node * NCLS + lane] = y0 - lse;
    if (has1) out[(size_t)node * NCLS + lane + 32] = y1 - lse;
}

// ---------------- launch ----------------
extern "C" void kernel_launch(void* const* d_in, const int* in_sizes, int n_in,
                              void* d_out, int out_size) {
    const float* x   = (const float*)d_in[0];
    const int*   ei  = (const int*)d_in[1];
    const float* W1  = (const float*)d_in[2];
    const float* as1 = (const float*)d_in[3];
    const float* ad1 = (const float*)d_in[4];
    const float* b1  = (const float*)d_in[5];
    const float* W2  = (const float*)d_in[6];
    const float* as2 = (const float*)d_in[7];
    const float* ad2 = (const float*)d_in[8];
    const float* b2  = (const float*)d_in[9];
    const float* ln0g = (const float*)d_in[10];
    const float* ln0b = (const float*)d_in[11];
    const float* ln1g = (const float*)d_in[12];
    const float* ln1b = (const float*)d_in[13];
    float* out = (float*)d_out;

    const int* srcp = ei;
    const int* dstp = ei + Ee;

    // Fork CSR build onto a side stream, overlapped with gemm1.
    cudaStream_t side = 0;
    cudaEvent_t evFork = 0, evJoin = 0;
    bool forked = (cudaStreamCreateWithFlags(&side, cudaStreamNonBlocking) == cudaSuccess) &&
                  (cudaEventCreateWithFlags(&evFork, cudaEventDisableTiming) == cudaSuccess) &&
                  (cudaEventCreateWithFlags(&evJoin, cudaEventDisableTiming) == cudaSuccess);

    if (forked) {
        cudaEventRecord(evFork, 0);
        cudaStreamWaitEvent(side, evFork, 0);
        zero_deg_kernel<<<(Nn + 255) / 256, 256, 0, side>>>();
        fill_kernel<<<(Ee + 255) / 256, 256, 0, side>>>(srcp, dstp);
        pad_kernel<<<(Nn + 255) / 256, 256, 0, side>>>();
        cudaEventRecord(evJoin, side);
    } else {
        zero_deg_kernel<<<(Nn + 255) / 256, 256>>>();
        fill_kernel<<<(Ee + 255) / 256, 256>>>(srcp, dstp);
        pad_kernel<<<(Nn + 255) / 256, 256>>>();
    }

    {
        dim3 grid(1, (Nn + 127) / 128);
        gemm_tc<0><<<grid, 256>>>(x, W1, as1, ad1);
    }
    if (forked) cudaStreamWaitEvent(0, evJoin, 0);
    agg1_kernel<<<(Nn * 32 + 255) / 256, 256>>>(b1, ln0g, ln0b);

    {
        dim3 grid(2, (Nn + 127) / 128);
        gemm_tc<1><<<grid, 256>>>(nullptr, W2, as2, ad2);
    }
    agg2_kernel<<<(Nn * 32 + 255) / 256, 256>>>(b2, ln1g, ln1b, out);
}